// round 8
// baseline (speedup 1.0000x reference)
#include <cuda_runtime.h>
#include <math.h>

#define Bn 4
#define KH 4
#define Cd 512
#define Dd 512
#define Nn 1024
#define NHh 8
#define QDq 64
#define THETAF (6.2831853071795865f / 1024.0f)
#define OUT_ELEMS 8388608   // output element count: real(res), float32, (4,4,512,1024)

// ---------------- per-batch scratch (device globals; ~100 MB total) ---------
__device__ float g_Er[3*KH*Dd*Nn];
__device__ float g_Ei[3*KH*Dd*Nn];
__device__ float g_S [NHh*Nn*Nn];
__device__ float g_Pr[KH*NHh*Nn];
__device__ float g_Pi[KH*NHh*Nn];
__device__ float g_ctxr[KH*Cd*Nn];
__device__ float g_ctxi[KH*Cd*Nn];

// guarded input load
static __device__ __forceinline__ float ldin(const float* p, int off, int n) {
    return (off >= 0 && off < n) ? p[off] : 0.0f;
}

// ---- k1(b): E[e,k,d,n] = sum_c emb[e,k,d,c] * x[b,k,c,n];  e==1 *= soft ----
__global__ void k1_embed(const float* __restrict__ embr, const float* __restrict__ embi,
                         const float* __restrict__ xr,   const float* __restrict__ xi,
                         const float* __restrict__ softr,const float* __restrict__ softi,
                         int n_embr, int n_embi, int n_xr, int n_xi,
                         int n_softr, int n_softi, int b)
{
    __shared__ __align__(16) float Asr[16][68], Asi[16][68], Bsr[16][64], Bsi[16][64];
    int z = blockIdx.z;                  // 0..11
    int e = z / KH, k = z % KH;
    int baseA = (e*KH + k)*Dd*Cd;
    int baseB = (b*KH + k)*Cd*Nn;
    int m0 = blockIdx.y*64, n0 = blockIdx.x*64;
    int tx = threadIdx.x, ty = threadIdx.y, tid = ty*16+tx;
    float cr[4][4] = {}, ci[4][4] = {};
    for (int c0 = 0; c0 < Cd; c0 += 16) {
        #pragma unroll
        for (int t = 0; t < 4; t++) {
            int idx = tid + t*256;
            int col = idx & 15, row = idx >> 4;          // col=c, row=d
            int ga = baseA + (m0+row)*Cd + c0+col;
            Asr[col][row] = ldin(embr, ga, n_embr);
            Asi[col][row] = ldin(embi, ga, n_embi);
        }
        #pragma unroll
        for (int t = 0; t < 4; t++) {
            int idx = tid + t*256;
            int col = idx & 63, row = idx >> 6;          // col=n, row=c
            int gb = baseB + (c0+row)*Nn + n0+col;
            Bsr[row][col] = ldin(xr, gb, n_xr);
            Bsi[row][col] = ldin(xi, gb, n_xi);
        }
        __syncthreads();
        #pragma unroll
        for (int kk = 0; kk < 16; kk++) {
            float4 arv = *(const float4*)&Asr[kk][ty*4];
            float4 aiv = *(const float4*)&Asi[kk][ty*4];
            float4 brv = *(const float4*)&Bsr[kk][tx*4];
            float4 biv = *(const float4*)&Bsi[kk][tx*4];
            float ar[4] = {arv.x,arv.y,arv.z,arv.w};
            float ai[4] = {aiv.x,aiv.y,aiv.z,aiv.w};
            float br[4] = {brv.x,brv.y,brv.z,brv.w};
            float bi[4] = {biv.x,biv.y,biv.z,biv.w};
            #pragma unroll
            for (int ii = 0; ii < 4; ii++)
                #pragma unroll
                for (int jj = 0; jj < 4; jj++) {
                    cr[ii][jj] = fmaf(ar[ii], br[jj], cr[ii][jj]);
                    cr[ii][jj] = fmaf(-ai[ii], bi[jj], cr[ii][jj]);
                    ci[ii][jj] = fmaf(ar[ii], bi[jj], ci[ii][jj]);
                    ci[ii][jj] = fmaf(ai[ii], br[jj], ci[ii][jj]);
                }
        }
        __syncthreads();
    }
    float* Eor = g_Er + (size_t)(e*KH + k)*Dd*Nn;
    float* Eoi = g_Ei + (size_t)(e*KH + k)*Dd*Nn;
    #pragma unroll
    for (int ii = 0; ii < 4; ii++) {
        int m = m0 + ty*4 + ii;
        float sr = 1.0f, si = 0.0f;
        if (e == 1) {
            int h = m >> 6;
            sr = ldin(softr, k*NHh + h, n_softr);
            si = ldin(softi, k*NHh + h, n_softi);
        }
        #pragma unroll
        for (int jj = 0; jj < 4; jj++) {
            int n = n0 + tx*4 + jj;
            Eor[(size_t)m*Nn + n] = cr[ii][jj]*sr - ci[ii][jj]*si;
            Eoi[(size_t)m*Nn + n] = cr[ii][jj]*si + ci[ii][jj]*sr;
        }
    }
}

// ---- kP(b): P[k,h,i] = soft[k,h]*cis(k*i*th)*sum_q conj(E0[k,h,q,i])*enc ----
__global__ void kP_pos(const float* __restrict__ encr, const float* __restrict__ enci,
                       const float* __restrict__ softr,const float* __restrict__ softi,
                       int n_encr, int n_enci, int n_softr, int n_softi)
{
    int z = blockIdx.y;
    int k = z / NHh, h = z % NHh;
    int i = blockIdx.x*256 + threadIdx.x;
    const float* E0r = g_Er + (size_t)k*Dd*Nn + (size_t)(h*QDq)*Nn;
    const float* E0i = g_Ei + (size_t)k*Dd*Nn + (size_t)(h*QDq)*Nn;
    float accr = 0.f, acci = 0.f;
    for (int q = 0; q < QDq; q++) {
        float er = E0r[(size_t)q*Nn + i], ei = E0i[(size_t)q*Nn + i];
        float nr = ldin(encr, (k*NHh + h)*QDq + q, n_encr);
        float ni = ldin(enci, (k*NHh + h)*QDq + q, n_enci);
        accr += er*nr + ei*ni;      // conj(E0) * enc
        acci += er*ni - ei*nr;
    }
    float sr = ldin(softr, k*NHh + h, n_softr);
    float si = ldin(softi, k*NHh + h, n_softi);
    float tr = accr*sr - acci*si, ti = accr*si + acci*sr;
    float s, c;
    sincosf(THETAF * (float)(k*i), &s, &c);
    int o = (k*NHh + h)*Nn + i;
    g_Pr[o] = tr*c - ti*s;
    g_Pi[o] = tr*s + ti*c;
}

// ---- k2(b): S[h,i,j] = |sum_{kq} E1[k,h,q,i]*conj(E0[k,h,q,j]) + pos| / 8 --
__global__ void k2_scores()
{
    __shared__ __align__(16) float Asr[16][64], Asi[16][64], Bsr[16][64], Bsi[16][64];
    int h = blockIdx.z;
    int i0 = blockIdx.y*64, j0 = blockIdx.x*64;
    int tx = threadIdx.x, ty = threadIdx.y, tid = ty*16+tx;
    const float* E1r = g_Er + (size_t)KH*Dd*Nn;
    const float* E1i = g_Ei + (size_t)KH*Dd*Nn;
    const float* E0r = g_Er;
    const float* E0i = g_Ei;
    float cr[4][4] = {}, ci[4][4] = {};
    for (int l0 = 0; l0 < KH*QDq; l0 += 16) {
        #pragma unroll
        for (int t = 0; t < 4; t++) {
            int idx = tid + t*256;
            int kk = idx >> 6, col = idx & 63;
            int l = l0 + kk; int kq = l >> 6; int q = l & 63;
            size_t rowoff = (size_t)(kq*Dd + h*QDq + q)*Nn;
            Asr[kk][col] = E1r[rowoff + i0 + col];
            Asi[kk][col] = E1i[rowoff + i0 + col];
            Bsr[kk][col] = E0r[rowoff + j0 + col];
            Bsi[kk][col] = -E0i[rowoff + j0 + col];  // Q = conj(E0)
        }
        __syncthreads();
        #pragma unroll
        for (int kk = 0; kk < 16; kk++) {
            float4 arv = *(const float4*)&Asr[kk][ty*4];
            float4 aiv = *(const float4*)&Asi[kk][ty*4];
            float4 brv = *(const float4*)&Bsr[kk][tx*4];
            float4 biv = *(const float4*)&Bsi[kk][tx*4];
            float ar[4] = {arv.x,arv.y,arv.z,arv.w};
            float ai[4] = {aiv.x,aiv.y,aiv.z,aiv.w};
            float br[4] = {brv.x,brv.y,brv.z,brv.w};
            float bi[4] = {biv.x,biv.y,biv.z,biv.w};
            #pragma unroll
            for (int ii = 0; ii < 4; ii++)
                #pragma unroll
                for (int jj = 0; jj < 4; jj++) {
                    cr[ii][jj] = fmaf(ar[ii], br[jj], cr[ii][jj]);
                    cr[ii][jj] = fmaf(-ai[ii], bi[jj], cr[ii][jj]);
                    ci[ii][jj] = fmaf(ar[ii], bi[jj], ci[ii][jj]);
                    ci[ii][jj] = fmaf(ai[ii], br[jj], ci[ii][jj]);
                }
        }
        __syncthreads();
    }
    // positional epilogue: pos[i,j] = sum_k P[k,h,i] * cis(-k*j*theta)
    float pr_[KH][4], pi_[KH][4];
    #pragma unroll
    for (int kq = 0; kq < KH; kq++)
        #pragma unroll
        for (int ii = 0; ii < 4; ii++) {
            int o = (kq*NHh + h)*Nn + i0 + ty*4 + ii;
            pr_[kq][ii] = g_Pr[o]; pi_[kq][ii] = g_Pi[o];
        }
    #pragma unroll
    for (int jj = 0; jj < 4; jj++) {
        int j = j0 + tx*4 + jj;
        float s, c;
        sincosf(-THETAF * (float)j, &s, &c);
        float wr = c, wi = s;
        float curr = 1.f, curi = 0.f;
        #pragma unroll
        for (int kq = 0; kq < KH; kq++) {
            #pragma unroll
            for (int ii = 0; ii < 4; ii++) {
                cr[ii][jj] += pr_[kq][ii]*curr - pi_[kq][ii]*curi;
                ci[ii][jj] += pr_[kq][ii]*curi + pi_[kq][ii]*curr;
            }
            float nr = curr*wr - curi*wi;
            curi = curr*wi + curi*wr;
            curr = nr;
        }
    }
    float* So = g_S + (size_t)h*Nn*Nn;
    #pragma unroll
    for (int ii = 0; ii < 4; ii++)
        #pragma unroll
        for (int jj = 0; jj < 4; jj++) {
            size_t o = (size_t)(i0 + ty*4 + ii)*Nn + j0 + tx*4 + jj;
            So[o] = sqrtf(cr[ii][jj]*cr[ii][jj] + ci[ii][jj]*ci[ii][jj]) * 0.125f;
        }
}

// ---- k3(b): softmax over i (in place in g_S), per (h, j) -------------------
__global__ void k3_softmax()
{
    __shared__ __align__(16) float red[8][33];
    int h = blockIdx.y;
    int tx = threadIdx.x, ty = threadIdx.y;     // 32 x 8
    int j = blockIdx.x*32 + tx;
    size_t base = (size_t)h*Nn*Nn;
    float mx = -1e30f;
    for (int i = ty; i < Nn; i += 8)
        mx = fmaxf(mx, g_S[base + (size_t)i*Nn + j]);
    red[ty][tx] = mx;
    __syncthreads();
    if (ty == 0) {
        float m = red[0][tx];
        #pragma unroll
        for (int r = 1; r < 8; r++) m = fmaxf(m, red[r][tx]);
        red[0][tx] = m;
    }
    __syncthreads();
    mx = red[0][tx];
    __syncthreads();
    float sum = 0.f;
    for (int i = ty; i < Nn; i += 8) {
        size_t o = base + (size_t)i*Nn + j;
        float e = expf(g_S[o] - mx);
        g_S[o] = e;
        sum += e;
    }
    red[ty][tx] = sum;
    __syncthreads();
    if (ty == 0) {
        float s = red[0][tx];
        #pragma unroll
        for (int r = 1; r < 8; r++) s += red[r][tx];
        red[0][tx] = s;
    }
    __syncthreads();
    float inv = 1.0f / red[0][tx];
    for (int i = ty; i < Nn; i += 8)
        g_S[base + (size_t)i*Nn + j] *= inv;
}

// ---- k4(b): ctx[k,h,q,j] = sum_i V[k,h,q,i] * S[h,i,j] ---------------------
__global__ void k4_ctx()
{
    __shared__ __align__(16) float Asr[16][68], Asi[16][68], Bs[16][64];
    int h = blockIdx.z;
    int m0 = blockIdx.y*64, j0 = blockIdx.x*64;
    int tx = threadIdx.x, ty = threadIdx.y, tid = ty*16+tx;
    const float* Vr = g_Er + (size_t)(2*KH)*Dd*Nn;
    const float* Vi = g_Ei + (size_t)(2*KH)*Dd*Nn;
    const float* S  = g_S  + (size_t)h*Nn*Nn;
    float cr[4][4] = {}, ci[4][4] = {};
    for (int i0 = 0; i0 < Nn; i0 += 16) {
        #pragma unroll
        for (int t = 0; t < 4; t++) {
            int idx = tid + t*256;
            int col = idx & 15, row = idx >> 4;      // col=i, row=l
            int l = m0 + row; int kq = l >> 6; int q = l & 63;
            size_t off = (size_t)(kq*Dd + h*QDq + q)*Nn + i0 + col;
            Asr[col][row] = Vr[off];
            Asi[col][row] = Vi[off];
        }
        #pragma unroll
        for (int t = 0; t < 4; t++) {
            int idx = tid + t*256;
            int row = idx >> 6, col = idx & 63;
            Bs[row][col] = S[(size_t)(i0 + row)*Nn + j0 + col];
        }
        __syncthreads();
        #pragma unroll
        for (int kk = 0; kk < 16; kk++) {
            float4 arv = *(const float4*)&Asr[kk][ty*4];
            float4 aiv = *(const float4*)&Asi[kk][ty*4];
            float4 bv  = *(const float4*)&Bs[kk][tx*4];
            float ar[4] = {arv.x,arv.y,arv.z,arv.w};
            float ai[4] = {aiv.x,aiv.y,aiv.z,aiv.w};
            float bb[4] = {bv.x,bv.y,bv.z,bv.w};
            #pragma unroll
            for (int ii = 0; ii < 4; ii++)
                #pragma unroll
                for (int jj = 0; jj < 4; jj++) {
                    cr[ii][jj] = fmaf(ar[ii], bb[jj], cr[ii][jj]);
                    ci[ii][jj] = fmaf(ai[ii], bb[jj], ci[ii][jj]);
                }
        }
        __syncthreads();
    }
    #pragma unroll
    for (int ii = 0; ii < 4; ii++) {
        int l = m0 + ty*4 + ii; int kq = l >> 6; int q = l & 63;
        size_t rowo = (size_t)(kq*Cd + h*QDq + q)*Nn;
        #pragma unroll
        for (int jj = 0; jj < 4; jj++) {
            size_t o = rowo + j0 + tx*4 + jj;
            g_ctxr[o] = cr[ii][jj];
            g_ctxi[o] = ci[ii][jj];
        }
    }
}

// ---- k5(b): res[b,k,d,j] = REAL( sum_c out[k,d,c] * ctx[k,c,j] ), float32 --
__global__ void k5_out(const float* __restrict__ outr, const float* __restrict__ outi,
                       float* __restrict__ res, int n_outr, int n_outi, int n_res,
                       int b)
{
    __shared__ __align__(16) float Asr[16][68], Asi[16][68], Bsr[16][64], Bsi[16][64];
    int k = blockIdx.z;
    int baseA = k*Dd*Cd;
    const float* Br_ = g_ctxr + (size_t)k*Cd*Nn;
    const float* Bi_ = g_ctxi + (size_t)k*Cd*Nn;
    int m0 = blockIdx.y*64, n0 = blockIdx.x*64;
    int tx = threadIdx.x, ty = threadIdx.y, tid = ty*16+tx;
    float cr[4][4] = {};
    for (int c0 = 0; c0 < Cd; c0 += 16) {
        #pragma unroll
        for (int t = 0; t < 4; t++) {
            int idx = tid + t*256;
            int col = idx & 15, row = idx >> 4;
            int ga = baseA + (m0+row)*Cd + c0+col;
            Asr[col][row] = ldin(outr, ga, n_outr);
            Asi[col][row] = ldin(outi, ga, n_outi);
        }
        #pragma unroll
        for (int t = 0; t < 4; t++) {
            int idx = tid + t*256;
            int col = idx & 63, row = idx >> 6;
            size_t gb = (size_t)(c0+row)*Nn + n0+col;
            Bsr[row][col] = Br_[gb];
            Bsi[row][col] = Bi_[gb];
        }
        __syncthreads();
        #pragma unroll
        for (int kk = 0; kk < 16; kk++) {
            float4 arv = *(const float4*)&Asr[kk][ty*4];
            float4 aiv = *(const float4*)&Asi[kk][ty*4];
            float4 brv = *(const float4*)&Bsr[kk][tx*4];
            float4 biv = *(const float4*)&Bsi[kk][tx*4];
            float ar[4] = {arv.x,arv.y,arv.z,arv.w};
            float ai[4] = {aiv.x,aiv.y,aiv.z,aiv.w};
            float br[4] = {brv.x,brv.y,brv.z,brv.w};
            float bi[4] = {biv.x,biv.y,biv.z,biv.w};
            #pragma unroll
            for (int ii = 0; ii < 4; ii++)
                #pragma unroll
                for (int jj = 0; jj < 4; jj++) {
                    // real part only: re(a*b) = ar*br - ai*bi
                    cr[ii][jj] = fmaf(ar[ii], br[jj], cr[ii][jj]);
                    cr[ii][jj] = fmaf(-ai[ii], bi[jj], cr[ii][jj]);
                }
        }
        __syncthreads();
    }
    int nlim = n_res < OUT_ELEMS ? n_res : OUT_ELEMS;
    #pragma unroll
    for (int ii = 0; ii < 4; ii++) {
        int d = m0 + ty*4 + ii;
        size_t rowo = ((size_t)(b*KH + k)*Dd + d)*Nn;
        #pragma unroll
        for (int jj = 0; jj < 4; jj++) {
            size_t o = rowo + n0 + tx*4 + jj;
            if (o < (size_t)nlim)
                res[o] = cr[ii][jj];
        }
    }
}

// ---------------- launch -----------------------------------------------------
static int classify_sz(int sz, int* elems) {
    switch (sz) {
        case 8388608:  *elems = sz;   return 0;  // x elems
        case 33554432: *elems = sz/4; return 0;  // x f32 bytes
        case 3145728:  *elems = sz;   return 1;  // emb
        case 12582912: *elems = sz/4; return 1;
        case 2048:     *elems = sz;   return 2;  // enc
        case 8192:     *elems = sz/4; return 2;
        case 32:       *elems = sz;   return 3;  // soft
        case 128:      *elems = sz/4; return 3;
        case 1048576:  *elems = sz;   return 4;  // out
        case 4194304:  *elems = sz/4; return 4;
        default: *elems = 0; return -1;
    }
}

extern "C" void kernel_launch(void* const* d_in, const int* in_sizes, int n_in,
                              void* d_out, int out_size)
{
    const float* pairs[5][2] = {};
    int psz[5][2] = {};
    int cnt[5] = {};
    bool ok = (n_in == 10) && d_out;
    if (ok) for (int i = 0; i < n_in; i++) if (!d_in[i]) ok = false;

    if (ok) {
        for (int i = 0; i < n_in; i++) {
            int el; int c = classify_sz(in_sizes[i], &el);
            if (c < 0 || cnt[c] >= 2) { ok = false; break; }
            pairs[c][cnt[c]] = (const float*)d_in[i];
            psz[c][cnt[c]] = el;
            cnt[c]++;
        }
        if (ok) for (int c = 0; c < 5; c++) if (cnt[c] != 2) ok = false;
    }

    const float *xr, *xi, *embr, *embi, *encr, *enci, *softr, *softi, *outr, *outi;
    int nxr, nxi, nembr, nembi, nencr, nenci, nsoftr, nsofti, noutr, nouti;
    if (ok) {
        // REAL index within pair: dict order (x first) -> 0; alphabetical -> 1.
        int el0; int c0 = classify_sz(in_sizes[0], &el0);
        int ri = (c0 == 1) ? 1 : 0;
        int im = 1 - ri;
        xr    = pairs[0][ri]; nxr    = psz[0][ri]; xi    = pairs[0][im]; nxi    = psz[0][im];
        embr  = pairs[1][ri]; nembr  = psz[1][ri]; embi  = pairs[1][im]; nembi  = psz[1][im];
        encr  = pairs[2][ri]; nencr  = psz[2][ri]; enci  = pairs[2][im]; nenci  = psz[2][im];
        softr = pairs[3][ri]; nsoftr = psz[3][ri]; softi = pairs[3][im]; nsofti = psz[3][im];
        outr  = pairs[4][ri]; noutr  = psz[4][ri]; outi  = pairs[4][im]; nouti  = psz[4][im];
    } else if (n_in >= 10 && d_out) {
        xr    = (const float*)d_in[0]; nxr    = in_sizes[0];
        xi    = (const float*)d_in[1]; nxi    = in_sizes[1];
        embr  = (const float*)d_in[2]; nembr  = in_sizes[2];
        embi  = (const float*)d_in[3]; nembi  = in_sizes[3];
        encr  = (const float*)d_in[4]; nencr  = in_sizes[4];
        enci  = (const float*)d_in[5]; nenci  = in_sizes[5];
        softr = (const float*)d_in[6]; nsoftr = in_sizes[6];
        softi = (const float*)d_in[7]; nsofti = in_sizes[7];
        outr  = (const float*)d_in[8]; noutr  = in_sizes[8];
        outi  = (const float*)d_in[9]; nouti  = in_sizes[9];
    } else {
        return;
    }

    dim3 blk(16, 16);
    for (int b = 0; b < Bn; b++) {
        k1_embed<<<dim3(Nn/64, Dd/64, 3*KH), blk>>>(embr, embi, xr, xi, softr, softi,
                                                    nembr, nembi, nxr, nxi,
                                                    nsoftr, nsofti, b);
        kP_pos<<<dim3(Nn/256, KH*NHh), 256>>>(encr, enci, softr, softi,
                                              nencr, nenci, nsoftr, nsofti);
        k2_scores<<<dim3(Nn/64, Nn/64, NHh), blk>>>();
        k3_softmax<<<dim3(Nn/32, NHh), dim3(32, 8)>>>();
        k4_ctx<<<dim3(Nn/64, (KH*QDq)/64, NHh), blk>>>();
        k5_out<<<dim3(Nn/64, Dd/64, KH), blk>>>(outr, outi, (float*)d_out,
                                                noutr, nouti, out_size, b);
    }
}

// round 9
// speedup vs baseline: 1.1341x; 1.1341x over previous
#include <cuda_runtime.h>
#include <math.h>

#define Bn 4
#define KH 4
#define Cd 512
#define Dd 512
#define Nn 1024
#define NHh 8
#define QDq 64
#define THETAF (6.2831853071795865f / 1024.0f)
#define OUT_ELEMS 8388608   // output: real(res), float32, (4,4,512,1024)

#define MT 128
#define NT 64
#define KT 16
#define ASTR 132

// ---------------- per-batch scratch (device globals) ------------------------
__device__ float g_Er[3*KH*Dd*Nn];
__device__ float g_Ei[3*KH*Dd*Nn];
__device__ float g_S [NHh*Nn*Nn];
__device__ float g_Pr[KH*NHh*Nn];
__device__ float g_Pi[KH*NHh*Nn];
__device__ float g_ctxr[KH*Cd*Nn];
__device__ float g_ctxi[KH*Cd*Nn];

typedef unsigned long long u64;
union F4U { float4 f; u64 u[2]; };

#define PK2(d, x) asm("mov.b64 %0, {%1, %1};" : "=l"(d) : "f"(x))
#define FMA2(d, a, b) asm("fma.rn.f32x2 %0, %1, %2, %0;" : "+l"(d) : "l"(a), "l"(b))

static __device__ __forceinline__ float2 unp2(u64 v) {
    float2 r; asm("mov.b64 {%0, %1}, %2;" : "=f"(r.x), "=f"(r.y) : "l"(v)); return r;
}
static __device__ __forceinline__ float ldin(const float* p, int off, int n) {
    return (off >= 0 && off < n) ? p[off] : 0.0f;
}

// ---- k1(b): E[e,k,d,n] = sum_c emb[e,k,d,c] * x[b,k,c,n];  e==1 *= soft ----
__global__ void __launch_bounds__(256, 2)
k1_embed(const float* __restrict__ embr, const float* __restrict__ embi,
         const float* __restrict__ xr,   const float* __restrict__ xi,
         const float* __restrict__ softr,const float* __restrict__ softi, int b)
{
    __shared__ __align__(16) float Asr[KT][ASTR], Asi[KT][ASTR];
    __shared__ __align__(16) float Bsr[KT][NT], Bsi[KT][NT];
    int z = blockIdx.z, e = z / KH, k = z % KH;
    const float* Ar = embr + (size_t)(e*KH + k)*Dd*Cd;
    const float* Ai = embi + (size_t)(e*KH + k)*Dd*Cd;
    const float* Br = xr + (size_t)(b*KH + k)*Cd*Nn;
    const float* Bi = xi + (size_t)(b*KH + k)*Cd*Nn;
    int m0 = blockIdx.y*MT, n0 = blockIdx.x*NT;
    int tid = threadIdx.x, tx = tid & 15, ty = tid >> 4;
    u64 crp[4][4] = {}, cip[4][4] = {};
    for (int c0 = 0; c0 < Cd; c0 += KT) {
        #pragma unroll
        for (int it = 0; it < 2; it++) {
            int g = tid + it*256, m = g >> 2, kc = (g & 3)*4;
            float4 a4 = *(const float4*)&Ar[(size_t)(m0+m)*Cd + c0 + kc];
            Asr[kc+0][m]=a4.x; Asr[kc+1][m]=a4.y; Asr[kc+2][m]=a4.z; Asr[kc+3][m]=a4.w;
            float4 b4 = *(const float4*)&Ai[(size_t)(m0+m)*Cd + c0 + kc];
            Asi[kc+0][m]=b4.x; Asi[kc+1][m]=b4.y; Asi[kc+2][m]=b4.z; Asi[kc+3][m]=b4.w;
        }
        {
            int kk = tid >> 4, nc = (tid & 15)*4;
            *(float4*)&Bsr[kk][nc] = *(const float4*)&Br[(size_t)(c0+kk)*Nn + n0 + nc];
            *(float4*)&Bsi[kk][nc] = *(const float4*)&Bi[(size_t)(c0+kk)*Nn + n0 + nc];
        }
        __syncthreads();
        #pragma unroll
        for (int kk = 0; kk < KT; kk++) {
            F4U ar0, ar1, ai0, ai1;
            ar0.f = *(const float4*)&Asr[kk][ty*8];
            ar1.f = *(const float4*)&Asr[kk][ty*8+4];
            ai0.f = *(const float4*)&Asi[kk][ty*8];
            ai1.f = *(const float4*)&Asi[kk][ty*8+4];
            u64 apr[4] = {ar0.u[0], ar0.u[1], ar1.u[0], ar1.u[1]};
            u64 api[4] = {ai0.u[0], ai0.u[1], ai1.u[0], ai1.u[1]};
            float4 brv = *(const float4*)&Bsr[kk][tx*4];
            float4 biv = *(const float4*)&Bsi[kk][tx*4];
            float brs[4] = {brv.x,brv.y,brv.z,brv.w};
            float bis[4] = {biv.x,biv.y,biv.z,biv.w};
            #pragma unroll
            for (int j = 0; j < 4; j++) {
                u64 bpr, bpi, bpn;
                PK2(bpr, brs[j]); PK2(bpi, bis[j]);
                float nb = -bis[j]; PK2(bpn, nb);
                #pragma unroll
                for (int mi = 0; mi < 4; mi++) {
                    FMA2(crp[mi][j], apr[mi], bpr);
                    FMA2(crp[mi][j], api[mi], bpn);
                    FMA2(cip[mi][j], apr[mi], bpi);
                    FMA2(cip[mi][j], api[mi], bpr);
                }
            }
        }
        __syncthreads();
    }
    float* Eor = g_Er + (size_t)(e*KH + k)*Dd*Nn;
    float* Eoi = g_Ei + (size_t)(e*KH + k)*Dd*Nn;
    #pragma unroll
    for (int r = 0; r < 8; r++) {
        int m = m0 + ty*8 + r, mi = r >> 1, hi = r & 1;
        float sr = 1.f, si = 0.f;
        if (e == 1) { int h = m >> 6; sr = softr[k*NHh+h]; si = softi[k*NHh+h]; }
        float vr[4], vi[4];
        #pragma unroll
        for (int j = 0; j < 4; j++) {
            float2 c2r = unp2(crp[mi][j]), c2i = unp2(cip[mi][j]);
            float cr = hi ? c2r.y : c2r.x, ci = hi ? c2i.y : c2i.x;
            vr[j] = cr*sr - ci*si; vi[j] = cr*si + ci*sr;
        }
        *(float4*)&Eor[(size_t)m*Nn + n0 + tx*4] = make_float4(vr[0],vr[1],vr[2],vr[3]);
        *(float4*)&Eoi[(size_t)m*Nn + n0 + tx*4] = make_float4(vi[0],vi[1],vi[2],vi[3]);
    }
}

// ---- kP(b): P[k,h,i] = soft[k,h]*cis(k*i*th)*sum_q conj(E0[k,h,q,i])*enc ----
__global__ void kP_pos(const float* __restrict__ encr, const float* __restrict__ enci,
                       const float* __restrict__ softr,const float* __restrict__ softi,
                       int n_encr, int n_enci, int n_softr, int n_softi)
{
    int z = blockIdx.y;
    int k = z / NHh, h = z % NHh;
    int i = blockIdx.x*256 + threadIdx.x;
    const float* E0r = g_Er + (size_t)k*Dd*Nn + (size_t)(h*QDq)*Nn;
    const float* E0i = g_Ei + (size_t)k*Dd*Nn + (size_t)(h*QDq)*Nn;
    float accr = 0.f, acci = 0.f;
    for (int q = 0; q < QDq; q++) {
        float er = E0r[(size_t)q*Nn + i], ei = E0i[(size_t)q*Nn + i];
        float nr = ldin(encr, (k*NHh + h)*QDq + q, n_encr);
        float ni = ldin(enci, (k*NHh + h)*QDq + q, n_enci);
        accr += er*nr + ei*ni;
        acci += er*ni - ei*nr;
    }
    float sr = ldin(softr, k*NHh + h, n_softr);
    float si = ldin(softi, k*NHh + h, n_softi);
    float tr = accr*sr - acci*si, ti = accr*si + acci*sr;
    float s, c;
    sincosf(THETAF * (float)(k*i), &s, &c);
    int o = (k*NHh + h)*Nn + i;
    g_Pr[o] = tr*c - ti*s;
    g_Pi[o] = tr*s + ti*c;
}

// ---- k2(b): S[h,i,j] = |sum_{kq} E1[k,h,q,i]*conj(E0[k,h,q,j]) + pos| / 8 --
__global__ void __launch_bounds__(256, 2) k2_scores()
{
    __shared__ __align__(16) float Asr[KT][ASTR], Asi[KT][ASTR];
    __shared__ __align__(16) float Bsr[KT][NT], Bsi[KT][NT];
    int h = blockIdx.z;
    int i0 = blockIdx.y*MT, j0 = blockIdx.x*NT;
    int tid = threadIdx.x, tx = tid & 15, ty = tid >> 4;
    const float* E1r = g_Er + (size_t)KH*Dd*Nn;
    const float* E1i = g_Ei + (size_t)KH*Dd*Nn;
    const float* E0r = g_Er;
    const float* E0i = g_Ei;
    u64 crp[4][4] = {}, cip[4][4] = {};
    for (int l0 = 0; l0 < KH*QDq; l0 += KT) {
        #pragma unroll
        for (int it = 0; it < 2; it++) {
            int g = tid + it*256, lk = g >> 5, ic = (g & 31)*4;
            int l = l0 + lk, kq = l >> 6, q = l & 63;
            size_t ro = (size_t)(kq*Dd + h*QDq + q)*Nn;
            *(float4*)&Asr[lk][ic] = *(const float4*)&E1r[ro + i0 + ic];
            *(float4*)&Asi[lk][ic] = *(const float4*)&E1i[ro + i0 + ic];
        }
        {
            int kk = tid >> 4, nc = (tid & 15)*4;
            int l = l0 + kk, kq = l >> 6, q = l & 63;
            size_t ro = (size_t)(kq*Dd + h*QDq + q)*Nn;
            *(float4*)&Bsr[kk][nc] = *(const float4*)&E0r[ro + j0 + nc];
            float4 c4 = *(const float4*)&E0i[ro + j0 + nc];
            *(float4*)&Bsi[kk][nc] = make_float4(-c4.x,-c4.y,-c4.z,-c4.w);  // conj
        }
        __syncthreads();
        #pragma unroll
        for (int kk = 0; kk < KT; kk++) {
            F4U ar0, ar1, ai0, ai1;
            ar0.f = *(const float4*)&Asr[kk][ty*8];
            ar1.f = *(const float4*)&Asr[kk][ty*8+4];
            ai0.f = *(const float4*)&Asi[kk][ty*8];
            ai1.f = *(const float4*)&Asi[kk][ty*8+4];
            u64 apr[4] = {ar0.u[0], ar0.u[1], ar1.u[0], ar1.u[1]};
            u64 api[4] = {ai0.u[0], ai0.u[1], ai1.u[0], ai1.u[1]};
            float4 brv = *(const float4*)&Bsr[kk][tx*4];
            float4 biv = *(const float4*)&Bsi[kk][tx*4];
            float brs[4] = {brv.x,brv.y,brv.z,brv.w};
            float bis[4] = {biv.x,biv.y,biv.z,biv.w};
            #pragma unroll
            for (int j = 0; j < 4; j++) {
                u64 bpr, bpi, bpn;
                PK2(bpr, brs[j]); PK2(bpi, bis[j]);
                float nb = -bis[j]; PK2(bpn, nb);
                #pragma unroll
                for (int mi = 0; mi < 4; mi++) {
                    FMA2(crp[mi][j], apr[mi], bpr);
                    FMA2(crp[mi][j], api[mi], bpn);
                    FMA2(cip[mi][j], apr[mi], bpi);
                    FMA2(cip[mi][j], api[mi], bpr);
                }
            }
        }
        __syncthreads();
    }
    // pos epilogue on packed accumulators: pos[i,j] = sum_k P[k,h,i]*cis(-k*j*th)
    #pragma unroll
    for (int j = 0; j < 4; j++) {
        int jj = j0 + tx*4 + j;
        float s, c;
        sincosf(-THETAF * (float)jj, &s, &c);
        float wr = c, wi = s, curr = 1.f, curi = 0.f;
        #pragma unroll
        for (int kq = 0; kq < KH; kq++) {
            u64 cp, sp, sn;
            PK2(cp, curr); PK2(sp, curi);
            float ns = -curi; PK2(sn, ns);
            #pragma unroll
            for (int mi = 0; mi < 4; mi++) {
                int i = i0 + ty*8 + mi*2;
                int off = (kq*NHh + h)*Nn + i;
                u64 ppr = *(const u64*)&g_Pr[off];
                u64 ppi = *(const u64*)&g_Pi[off];
                FMA2(crp[mi][j], ppr, cp);
                FMA2(crp[mi][j], ppi, sn);
                FMA2(cip[mi][j], ppr, sp);
                FMA2(cip[mi][j], ppi, cp);
            }
            float nr = curr*wr - curi*wi;
            curi = curr*wi + curi*wr;
            curr = nr;
        }
    }
    float* So = g_S + (size_t)h*Nn*Nn;
    #pragma unroll
    for (int r = 0; r < 8; r++) {
        int i = i0 + ty*8 + r, mi = r >> 1, hi = r & 1;
        float sv[4];
        #pragma unroll
        for (int j = 0; j < 4; j++) {
            float2 c2r = unp2(crp[mi][j]), c2i = unp2(cip[mi][j]);
            float cr = hi ? c2r.y : c2r.x, ci = hi ? c2i.y : c2i.x;
            sv[j] = sqrtf(cr*cr + ci*ci) * 0.125f;
        }
        *(float4*)&So[(size_t)i*Nn + j0 + tx*4] = make_float4(sv[0],sv[1],sv[2],sv[3]);
    }
}

// ---- k3(b): softmax over i (in place in g_S), per (h, j) -------------------
__global__ void k3_softmax()
{
    __shared__ __align__(16) float red[8][33];
    int h = blockIdx.y;
    int tx = threadIdx.x, ty = threadIdx.y;     // 32 x 8
    int j = blockIdx.x*32 + tx;
    size_t base = (size_t)h*Nn*Nn;
    float mx = -1e30f;
    for (int i = ty; i < Nn; i += 8)
        mx = fmaxf(mx, g_S[base + (size_t)i*Nn + j]);
    red[ty][tx] = mx;
    __syncthreads();
    if (ty == 0) {
        float m = red[0][tx];
        #pragma unroll
        for (int r = 1; r < 8; r++) m = fmaxf(m, red[r][tx]);
        red[0][tx] = m;
    }
    __syncthreads();
    mx = red[0][tx];
    __syncthreads();
    float sum = 0.f;
    for (int i = ty; i < Nn; i += 8) {
        size_t o = base + (size_t)i*Nn + j;
        float e = expf(g_S[o] - mx);
        g_S[o] = e;
        sum += e;
    }
    red[ty][tx] = sum;
    __syncthreads();
    if (ty == 0) {
        float s = red[0][tx];
        #pragma unroll
        for (int r = 1; r < 8; r++) s += red[r][tx];
        red[0][tx] = s;
    }
    __syncthreads();
    float inv = 1.0f / red[0][tx];
    for (int i = ty; i < Nn; i += 8)
        g_S[base + (size_t)i*Nn + j] *= inv;
}

// ---- k4(b): ctx[k,h,q,j] = sum_i V[k,h,q,i] * S[h,i,j]  (complex x real) ---
__global__ void __launch_bounds__(256, 2) k4_ctx()
{
    __shared__ __align__(16) float Asr[KT][ASTR], Asi[KT][ASTR];
    __shared__ __align__(16) float Bs[KT][NT];
    int h = blockIdx.z;
    int m0 = blockIdx.y*MT, j0 = blockIdx.x*NT;
    int tid = threadIdx.x, tx = tid & 15, ty = tid >> 4;
    const float* Vr = g_Er + (size_t)(2*KH)*Dd*Nn;
    const float* Vi = g_Ei + (size_t)(2*KH)*Dd*Nn;
    const float* S  = g_S + (size_t)h*Nn*Nn;
    u64 crp[4][4] = {}, cip[4][4] = {};
    for (int c0 = 0; c0 < Nn; c0 += KT) {
        #pragma unroll
        for (int it = 0; it < 2; it++) {
            int g = tid + it*256, m = g >> 2, kc = (g & 3)*4;
            int l = m0 + m, kq = l >> 6, q = l & 63;
            size_t ro = (size_t)(kq*Dd + h*QDq + q)*Nn;
            float4 a4 = *(const float4*)&Vr[ro + c0 + kc];
            Asr[kc+0][m]=a4.x; Asr[kc+1][m]=a4.y; Asr[kc+2][m]=a4.z; Asr[kc+3][m]=a4.w;
            float4 b4 = *(const float4*)&Vi[ro + c0 + kc];
            Asi[kc+0][m]=b4.x; Asi[kc+1][m]=b4.y; Asi[kc+2][m]=b4.z; Asi[kc+3][m]=b4.w;
        }
        {
            int kk = tid >> 4, nc = (tid & 15)*4;
            *(float4*)&Bs[kk][nc] = *(const float4*)&S[(size_t)(c0+kk)*Nn + j0 + nc];
        }
        __syncthreads();
        #pragma unroll
        for (int kk = 0; kk < KT; kk++) {
            F4U ar0, ar1, ai0, ai1;
            ar0.f = *(const float4*)&Asr[kk][ty*8];
            ar1.f = *(const float4*)&Asr[kk][ty*8+4];
            ai0.f = *(const float4*)&Asi[kk][ty*8];
            ai1.f = *(const float4*)&Asi[kk][ty*8+4];
            u64 apr[4] = {ar0.u[0], ar0.u[1], ar1.u[0], ar1.u[1]};
            u64 api[4] = {ai0.u[0], ai0.u[1], ai1.u[0], ai1.u[1]};
            float4 bv = *(const float4*)&Bs[kk][tx*4];
            float bs[4] = {bv.x,bv.y,bv.z,bv.w};
            #pragma unroll
            for (int j = 0; j < 4; j++) {
                u64 bp; PK2(bp, bs[j]);
                #pragma unroll
                for (int mi = 0; mi < 4; mi++) {
                    FMA2(crp[mi][j], apr[mi], bp);
                    FMA2(cip[mi][j], api[mi], bp);
                }
            }
        }
        __syncthreads();
    }
    #pragma unroll
    for (int r = 0; r < 8; r++) {
        int l = m0 + ty*8 + r, mi = r >> 1, hi = r & 1;
        int kq = l >> 6, q = l & 63;
        size_t ro = (size_t)(kq*Cd + h*QDq + q)*Nn;
        float vr[4], vi[4];
        #pragma unroll
        for (int j = 0; j < 4; j++) {
            float2 c2r = unp2(crp[mi][j]), c2i = unp2(cip[mi][j]);
            vr[j] = hi ? c2r.y : c2r.x;
            vi[j] = hi ? c2i.y : c2i.x;
        }
        *(float4*)&g_ctxr[ro + j0 + tx*4] = make_float4(vr[0],vr[1],vr[2],vr[3]);
        *(float4*)&g_ctxi[ro + j0 + tx*4] = make_float4(vi[0],vi[1],vi[2],vi[3]);
    }
}

// ---- k5(b): res[b,k,d,j] = REAL( sum_c out[k,d,c] * ctx[k,c,j] ) -----------
__global__ void __launch_bounds__(256, 2)
k5_out(const float* __restrict__ outr, const float* __restrict__ outi,
       float* __restrict__ res, int n_res, int b)
{
    __shared__ __align__(16) float Asr[KT][ASTR], Asi[KT][ASTR];
    __shared__ __align__(16) float Bsr[KT][NT], Bsi[KT][NT];
    int k = blockIdx.z;
    const float* Ar = outr + (size_t)k*Dd*Cd;
    const float* Ai = outi + (size_t)k*Dd*Cd;
    const float* Br = g_ctxr + (size_t)k*Cd*Nn;
    const float* Bi = g_ctxi + (size_t)k*Cd*Nn;
    int m0 = blockIdx.y*MT, n0 = blockIdx.x*NT;
    int tid = threadIdx.x, tx = tid & 15, ty = tid >> 4;
    u64 crp[4][4] = {};
    for (int c0 = 0; c0 < Cd; c0 += KT) {
        #pragma unroll
        for (int it = 0; it < 2; it++) {
            int g = tid + it*256, m = g >> 2, kc = (g & 3)*4;
            float4 a4 = *(const float4*)&Ar[(size_t)(m0+m)*Cd + c0 + kc];
            Asr[kc+0][m]=a4.x; Asr[kc+1][m]=a4.y; Asr[kc+2][m]=a4.z; Asr[kc+3][m]=a4.w;
            float4 b4 = *(const float4*)&Ai[(size_t)(m0+m)*Cd + c0 + kc];
            Asi[kc+0][m]=b4.x; Asi[kc+1][m]=b4.y; Asi[kc+2][m]=b4.z; Asi[kc+3][m]=b4.w;
        }
        {
            int kk = tid >> 4, nc = (tid & 15)*4;
            *(float4*)&Bsr[kk][nc] = *(const float4*)&Br[(size_t)(c0+kk)*Nn + n0 + nc];
            *(float4*)&Bsi[kk][nc] = *(const float4*)&Bi[(size_t)(c0+kk)*Nn + n0 + nc];
        }
        __syncthreads();
        #pragma unroll
        for (int kk = 0; kk < KT; kk++) {
            F4U ar0, ar1, ai0, ai1;
            ar0.f = *(const float4*)&Asr[kk][ty*8];
            ar1.f = *(const float4*)&Asr[kk][ty*8+4];
            ai0.f = *(const float4*)&Asi[kk][ty*8];
            ai1.f = *(const float4*)&Asi[kk][ty*8+4];
            u64 apr[4] = {ar0.u[0], ar0.u[1], ar1.u[0], ar1.u[1]};
            u64 api[4] = {ai0.u[0], ai0.u[1], ai1.u[0], ai1.u[1]};
            float4 brv = *(const float4*)&Bsr[kk][tx*4];
            float4 biv = *(const float4*)&Bsi[kk][tx*4];
            float brs[4] = {brv.x,brv.y,brv.z,brv.w};
            float bis[4] = {biv.x,biv.y,biv.z,biv.w};
            #pragma unroll
            for (int j = 0; j < 4; j++) {
                u64 bpr, bpn;
                PK2(bpr, brs[j]);
                float nb = -bis[j]; PK2(bpn, nb);
                #pragma unroll
                for (int mi = 0; mi < 4; mi++) {
                    FMA2(crp[mi][j], apr[mi], bpr);
                    FMA2(crp[mi][j], api[mi], bpn);
                }
            }
        }
        __syncthreads();
    }
    int nlim = n_res < OUT_ELEMS ? n_res : OUT_ELEMS;
    #pragma unroll
    for (int r = 0; r < 8; r++) {
        int m = m0 + ty*8 + r, mi = r >> 1, hi = r & 1;
        size_t rowo = ((size_t)(b*KH + k)*Dd + m)*Nn;
        float v[4];
        #pragma unroll
        for (int j = 0; j < 4; j++) {
            float2 c2 = unp2(crp[mi][j]);
            v[j] = hi ? c2.y : c2.x;
        }
        size_t o = rowo + n0 + tx*4;
        if (o + 4 <= (size_t)nlim) {
            *(float4*)&res[o] = make_float4(v[0],v[1],v[2],v[3]);
        } else {
            #pragma unroll
            for (int j = 0; j < 4; j++)
                if (o + j < (size_t)nlim) res[o + j] = v[j];
        }
    }
}

// ---------------- launch -----------------------------------------------------
static int classify_sz(int sz, int* elems) {
    switch (sz) {
        case 8388608:  *elems = sz;   return 0;  // x elems
        case 33554432: *elems = sz/4; return 0;  // x f32 bytes
        case 3145728:  *elems = sz;   return 1;  // emb
        case 12582912: *elems = sz/4; return 1;
        case 2048:     *elems = sz;   return 2;  // enc
        case 8192:     *elems = sz/4; return 2;
        case 32:       *elems = sz;   return 3;  // soft
        case 128:      *elems = sz/4; return 3;
        case 1048576:  *elems = sz;   return 4;  // out
        case 4194304:  *elems = sz/4; return 4;
        default: *elems = 0; return -1;
    }
}

extern "C" void kernel_launch(void* const* d_in, const int* in_sizes, int n_in,
                              void* d_out, int out_size)
{
    const float* pairs[5][2] = {};
    int psz[5][2] = {};
    int cnt[5] = {};
    bool ok = (n_in == 10) && d_out;
    if (ok) for (int i = 0; i < n_in; i++) if (!d_in[i]) ok = false;

    if (ok) {
        for (int i = 0; i < n_in; i++) {
            int el; int c = classify_sz(in_sizes[i], &el);
            if (c < 0 || cnt[c] >= 2) { ok = false; break; }
            pairs[c][cnt[c]] = (const float*)d_in[i];
            psz[c][cnt[c]] = el;
            cnt[c]++;
        }
        if (ok) for (int c = 0; c < 5; c++) if (cnt[c] != 2) ok = false;
    }

    const float *xr, *xi, *embr, *embi, *encr, *enci, *softr, *softi, *outr, *outi;
    int nencr, nenci, nsoftr, nsofti;
    if (ok) {
        int el0; int c0 = classify_sz(in_sizes[0], &el0);
        int ri = (c0 == 1) ? 1 : 0;
        int im = 1 - ri;
        xr    = pairs[0][ri]; xi    = pairs[0][im];
        embr  = pairs[1][ri]; embi  = pairs[1][im];
        encr  = pairs[2][ri]; nencr  = psz[2][ri]; enci  = pairs[2][im]; nenci  = psz[2][im];
        softr = pairs[3][ri]; nsoftr = psz[3][ri]; softi = pairs[3][im]; nsofti = psz[3][im];
        outr  = pairs[4][ri]; outi  = pairs[4][im];
    } else if (n_in >= 10 && d_out) {
        xr    = (const float*)d_in[0]; xi    = (const float*)d_in[1];
        embr  = (const float*)d_in[2]; embi  = (const float*)d_in[3];
        encr  = (const float*)d_in[4]; nencr  = in_sizes[4];
        enci  = (const float*)d_in[5]; nenci  = in_sizes[5];
        softr = (const float*)d_in[6]; nsoftr = in_sizes[6];
        softi = (const float*)d_in[7]; nsofti = in_sizes[7];
        outr  = (const float*)d_in[8]; outi  = (const float*)d_in[9];
    } else {
        return;
    }

    for (int b = 0; b < Bn; b++) {
        k1_embed<<<dim3(Nn/NT, Dd/MT, 3*KH), 256>>>(embr, embi, xr, xi, softr, softi, b);
        kP_pos<<<dim3(Nn/256, KH*NHh), 256>>>(encr, enci, softr, softi,
                                              nencr, nenci, nsoftr, nsofti);
        k2_scores<<<dim3(Nn/NT, Nn/MT, NHh), 256>>>();
        k3_softmax<<<dim3(Nn/32, NHh), dim3(32, 8)>>>();
        k4_ctx<<<dim3(Nn/NT, (KH*QDq)/MT, NHh), 256>>>();
        k5_out<<<dim3(Nn/NT, Dd/MT, KH), 256>>>(outr, outi, (float*)d_out, out_size, b);
    }
}

// round 11
// speedup vs baseline: 1.1447x; 1.0094x over previous
#include <cuda_runtime.h>
#include <cuda_bf16.h>
#include <math.h>

#define Bn 4
#define KH 4
#define Cd 512
#define Dd 512
#define Nn 1024
#define NHh 8
#define QDq 64
#define THETAF (6.2831853071795865f / 1024.0f)
#define OUT_ELEMS 8388608

#define MT 128
#define NT 64
#define KT 16
#define ASTR 132

// ---------------- per-batch scratch ------------------------------------------
__device__ float g_Er[3*KH*Dd*Nn];
__device__ float g_Ei[3*KH*Dd*Nn];
__device__ float g_S [NHh*Nn*Nn];
__device__ float g_Pr[KH*NHh*Nn];
__device__ float g_Pi[KH*NHh*Nn];
__device__ float g_ctxr[KH*Cd*Nn];
__device__ float g_ctxi[KH*Cd*Nn];

typedef unsigned long long u64;
typedef unsigned int u32;
union F4U { float4 f; u64 u[2]; };

#define PK2(d, x) asm("mov.b64 %0, {%1, %1};" : "=l"(d) : "f"(x))
#define FMA2(d, a, b) asm("fma.rn.f32x2 %0, %1, %2, %0;" : "+l"(d) : "l"(a), "l"(b))

static __device__ __forceinline__ float2 unp2(u64 v) {
    float2 r; asm("mov.b64 {%0, %1}, %2;" : "=f"(r.x), "=f"(r.y) : "l"(v)); return r;
}
static __device__ __forceinline__ float ldin(const float* p, int off, int n) {
    return (off >= 0 && off < n) ? p[off] : 0.0f;
}
static __device__ __forceinline__ u32 smem_u32(const void* p) {
    u32 a; asm("{ .reg .u64 t; cvta.to.shared.u64 t, %1; cvt.u32.u64 %0, t; }"
               : "=r"(a) : "l"(p));
    return a;
}

// ---------------- mma.sync helpers (baseline PTX, works on sm_103) ----------
#define LDSM4(r, a) asm volatile( \
    "ldmatrix.sync.aligned.m8n8.x4.shared.b16 {%0,%1,%2,%3}, [%4];" \
    : "=r"((r)[0]),"=r"((r)[1]),"=r"((r)[2]),"=r"((r)[3]) : "r"(a))
#define LDSM2T(r, a) asm volatile( \
    "ldmatrix.sync.aligned.m8n8.x2.trans.shared.b16 {%0,%1}, [%2];" \
    : "=r"((r)[0]),"=r"((r)[1]) : "r"(a))
#define MMABF(d, a, b) asm volatile( \
    "mma.sync.aligned.m16n8k16.row.col.f32.bf16.bf16.f32 " \
    "{%0,%1,%2,%3},{%4,%5,%6,%7},{%8,%9},{%0,%1,%2,%3};" \
    : "+f"((d)[0]),"+f"((d)[1]),"+f"((d)[2]),"+f"((d)[3]) \
    : "r"((a)[0]),"r"((a)[1]),"r"((a)[2]),"r"((a)[3]),"r"((b)[0]),"r"((b)[1]))

static __device__ __forceinline__ unsigned short bfh(float v) {
    __nv_bfloat16 h = __float2bfloat16(v);
    return *(unsigned short*)&h;
}
static __device__ __forceinline__ float bf2f(unsigned short s) {
    __nv_bfloat16 h = *(__nv_bfloat16*)&s;
    return __bfloat162float(h);
}
static __device__ __forceinline__ void split3(float v, unsigned short* o) {
    unsigned short h = bfh(v);
    float r1 = v - bf2f(h);
    unsigned short m = bfh(r1);
    unsigned short l = bfh(r1 - bf2f(m));
    o[0] = h; o[1] = m; o[2] = l;
}
static __device__ __forceinline__ u64 pk4(const unsigned short* s0,
                                          const unsigned short* s1,
                                          const unsigned short* s2,
                                          const unsigned short* s3, int idx) {
    return (u64)s0[idx] | ((u64)s1[idx] << 16) | ((u64)s2[idx] << 32) | ((u64)s3[idx] << 48);
}

// A planes (emb): 0-2 = r h/m/l, 3-5 = i h/m/l. row stride 40 bf16 = 80 B.
// B planes (x):   0-2 = r, 3-5 = i, 6-8 = -i.  row stride 136 bf16 = 272 B.
#define APL 10240          // 128*80
#define BPL 8704           // 32*272
#define K1_SMEM (6*APL + 9*BPL)   // 61440 + 78336 = 139776

// ==== k1 (mma.sync bf16x6): E[e,k,d,n] = sum_c emb[e,k,d,c]*x[b,k,c,n] ======
__global__ void __launch_bounds__(512, 1)
k1_mma(const float* __restrict__ embr, const float* __restrict__ embi,
       const float* __restrict__ xr,   const float* __restrict__ xi,
       const float* __restrict__ softr,const float* __restrict__ softi, int b)
{
    extern __shared__ char sm[];
    u32 smA = smem_u32(sm);
    u32 smB = smA + 6*APL;
    int tid = threadIdx.x, wid = tid >> 5, lane = tid & 31;
    int wm = wid >> 2, wn = wid & 3;           // warp grid 4x4 (m x n)
    int z = blockIdx.z, e = z / KH, k = z % KH;
    int n0 = blockIdx.x * 128, d0 = blockIdx.y * 128;
    size_t eb = (size_t)(e*KH + k)*Dd*Cd;
    size_t xb = (size_t)(b*KH + k)*Cd*Nn;

    const int PA[6] = {0, 0, 1, 0, 2, 1};
    const int PB[6] = {0, 1, 0, 2, 0, 1};

    float dr[2][4][4] = {}, di[2][4][4] = {};

    u32 aRowOff = (u32)((wm*32 + (lane & 15))*80 + (lane >> 4)*16);
    u32 bColOff = (u32)((wn*32)*2);

    for (int c0 = 0; c0 < Cd; c0 += 32) {
        // ---- stage A (emb tile 128 x 32), 2 iters x 512 thr
        #pragma unroll
        for (int it = 0; it < 2; it++) {
            int t = tid + it*512;               // 1024 tasks
            int m = t >> 3, c4 = (t & 7)*4;
            size_t ga = eb + (size_t)(d0 + m)*Cd + c0 + c4;
            float4 vr = *(const float4*)&embr[ga];
            float4 vi = *(const float4*)&embi[ga];
            unsigned short h[4], mm[4], l[4], s3[3];
            float rs[4] = {vr.x, vr.y, vr.z, vr.w};
            #pragma unroll
            for (int j = 0; j < 4; j++) { split3(rs[j], s3); h[j]=s3[0]; mm[j]=s3[1]; l[j]=s3[2]; }
            u32 wo = (u32)(m*80 + c4*2);
            *(u64*)(sm + 0*APL + wo) = (u64)h[0]  | ((u64)h[1]<<16)  | ((u64)h[2]<<32)  | ((u64)h[3]<<48);
            *(u64*)(sm + 1*APL + wo) = (u64)mm[0] | ((u64)mm[1]<<16) | ((u64)mm[2]<<32) | ((u64)mm[3]<<48);
            *(u64*)(sm + 2*APL + wo) = (u64)l[0]  | ((u64)l[1]<<16)  | ((u64)l[2]<<32)  | ((u64)l[3]<<48);
            float is[4] = {vi.x, vi.y, vi.z, vi.w};
            #pragma unroll
            for (int j = 0; j < 4; j++) { split3(is[j], s3); h[j]=s3[0]; mm[j]=s3[1]; l[j]=s3[2]; }
            *(u64*)(sm + 3*APL + wo) = (u64)h[0]  | ((u64)h[1]<<16)  | ((u64)h[2]<<32)  | ((u64)h[3]<<48);
            *(u64*)(sm + 4*APL + wo) = (u64)mm[0] | ((u64)mm[1]<<16) | ((u64)mm[2]<<32) | ((u64)mm[3]<<48);
            *(u64*)(sm + 5*APL + wo) = (u64)l[0]  | ((u64)l[1]<<16)  | ((u64)l[2]<<32)  | ((u64)l[3]<<48);
        }
        // ---- stage B (x tile 32 x 128): r, i, -i planes
        #pragma unroll
        for (int it = 0; it < 2; it++) {
            int t = tid + it*512;               // 1024 tasks
            int c = t >> 5, n4 = (t & 31)*4;
            size_t ga = xb + (size_t)(c0 + c)*Nn + n0 + n4;
            float4 vr = *(const float4*)&xr[ga];
            float4 vi = *(const float4*)&xi[ga];
            unsigned short h[4], mm[4], l[4], s3[3];
            u32 wo = (u32)(c*272 + n4*2);
            float rs[4] = {vr.x, vr.y, vr.z, vr.w};
            #pragma unroll
            for (int j = 0; j < 4; j++) { split3(rs[j], s3); h[j]=s3[0]; mm[j]=s3[1]; l[j]=s3[2]; }
            char* bb = sm + 6*APL;
            *(u64*)(bb + 0*BPL + wo) = (u64)h[0]  | ((u64)h[1]<<16)  | ((u64)h[2]<<32)  | ((u64)h[3]<<48);
            *(u64*)(bb + 1*BPL + wo) = (u64)mm[0] | ((u64)mm[1]<<16) | ((u64)mm[2]<<32) | ((u64)mm[3]<<48);
            *(u64*)(bb + 2*BPL + wo) = (u64)l[0]  | ((u64)l[1]<<16)  | ((u64)l[2]<<32)  | ((u64)l[3]<<48);
            float is[4] = {vi.x, vi.y, vi.z, vi.w};
            #pragma unroll
            for (int j = 0; j < 4; j++) { split3(is[j], s3); h[j]=s3[0]; mm[j]=s3[1]; l[j]=s3[2]; }
            *(u64*)(bb + 3*BPL + wo) = (u64)h[0]  | ((u64)h[1]<<16)  | ((u64)h[2]<<32)  | ((u64)h[3]<<48);
            *(u64*)(bb + 4*BPL + wo) = (u64)mm[0] | ((u64)mm[1]<<16) | ((u64)mm[2]<<32) | ((u64)mm[3]<<48);
            *(u64*)(bb + 5*BPL + wo) = (u64)l[0]  | ((u64)l[1]<<16)  | ((u64)l[2]<<32)  | ((u64)l[3]<<48);
            #pragma unroll
            for (int j = 0; j < 4; j++) { split3(-is[j], s3); h[j]=s3[0]; mm[j]=s3[1]; l[j]=s3[2]; }
            *(u64*)(bb + 6*BPL + wo) = (u64)h[0]  | ((u64)h[1]<<16)  | ((u64)h[2]<<32)  | ((u64)h[3]<<48);
            *(u64*)(bb + 7*BPL + wo) = (u64)mm[0] | ((u64)mm[1]<<16) | ((u64)mm[2]<<32) | ((u64)mm[3]<<48);
            *(u64*)(bb + 8*BPL + wo) = (u64)l[0]  | ((u64)l[1]<<16)  | ((u64)l[2]<<32)  | ((u64)l[3]<<48);
        }
        __syncthreads();
        // ---- compute
        #pragma unroll
        for (int ks = 0; ks < 2; ks++) {
            #pragma unroll
            for (int s = 0; s < 6; s++) {
                u32 ar0[4], ar1[4], ai0[4], ai1[4];
                u32 abase = smA + aRowOff + (u32)(ks*32);
                LDSM4(ar0, abase + PA[s]*APL);
                LDSM4(ar1, abase + PA[s]*APL + 16*80);
                LDSM4(ai0, abase + (3+PA[s])*APL);
                LDSM4(ai1, abase + (3+PA[s])*APL + 16*80);
                u32 bbase = smB + (u32)((ks*16 + (lane & 15))*272) + bColOff;
                #pragma unroll
                for (int nt = 0; nt < 4; nt++) {
                    u32 br[2], bi[2], bn[2];
                    u32 boff = bbase + (u32)(nt*16);
                    LDSM2T(br, boff + PB[s]*BPL);
                    LDSM2T(bi, boff + (3+PB[s])*BPL);
                    LDSM2T(bn, boff + (6+PB[s])*BPL);
                    MMABF(dr[0][nt], ar0, br); MMABF(dr[0][nt], ai0, bn);
                    MMABF(di[0][nt], ar0, bi); MMABF(di[0][nt], ai0, br);
                    MMABF(dr[1][nt], ar1, br); MMABF(dr[1][nt], ai1, bn);
                    MMABF(di[1][nt], ar1, bi); MMABF(di[1][nt], ai1, br);
                }
            }
        }
        __syncthreads();
    }

    // ---- epilogue: soft fold (e==1), store E f32
    float* Eor = g_Er + (size_t)(e*KH + k)*Dd*Nn;
    float* Eoi = g_Ei + (size_t)(e*KH + k)*Dd*Nn;
    #pragma unroll
    for (int mt = 0; mt < 2; mt++) {
        #pragma unroll
        for (int ch = 0; ch < 2; ch++) {
            int d = d0 + wm*32 + mt*16 + (lane >> 2) + ch*8;
            float sr = 1.f, si = 0.f;
            if (e == 1) { int h = d >> 6; sr = softr[k*NHh+h]; si = softi[k*NHh+h]; }
            #pragma unroll
            for (int nt = 0; nt < 4; nt++) {
                int n = n0 + wn*32 + nt*8 + (lane & 3)*2;
                float cr0 = dr[mt][nt][ch*2],   ci0 = di[mt][nt][ch*2];
                float cr1 = dr[mt][nt][ch*2+1], ci1 = di[mt][nt][ch*2+1];
                float2 vrp = make_float2(cr0*sr - ci0*si, cr1*sr - ci1*si);
                float2 vip = make_float2(cr0*si + ci0*sr, cr1*si + ci1*sr);
                *(float2*)&Eor[(size_t)d*Nn + n] = vrp;
                *(float2*)&Eoi[(size_t)d*Nn + n] = vip;
            }
        }
    }
}

// ---- kP(b) ------------------------------------------------------------------
__global__ void kP_pos(const float* __restrict__ encr, const float* __restrict__ enci,
                       const float* __restrict__ softr,const float* __restrict__ softi,
                       int n_encr, int n_enci, int n_softr, int n_softi)
{
    int z = blockIdx.y;
    int k = z / NHh, h = z % NHh;
    int i = blockIdx.x*256 + threadIdx.x;
    const float* E0r = g_Er + (size_t)k*Dd*Nn + (size_t)(h*QDq)*Nn;
    const float* E0i = g_Ei + (size_t)k*Dd*Nn + (size_t)(h*QDq)*Nn;
    float accr = 0.f, acci = 0.f;
    for (int q = 0; q < QDq; q++) {
        float er = E0r[(size_t)q*Nn + i], ei = E0i[(size_t)q*Nn + i];
        float nr = ldin(encr, (k*NHh + h)*QDq + q, n_encr);
        float ni = ldin(enci, (k*NHh + h)*QDq + q, n_enci);
        accr += er*nr + ei*ni;
        acci += er*ni - ei*nr;
    }
    float sr = ldin(softr, k*NHh + h, n_softr);
    float si = ldin(softi, k*NHh + h, n_softi);
    float tr = accr*sr - acci*si, ti = accr*si + acci*sr;
    float s, c;
    sincosf(THETAF * (float)(k*i), &s, &c);
    int o = (k*NHh + h)*Nn + i;
    g_Pr[o] = tr*c - ti*s;
    g_Pi[o] = tr*s + ti*c;
}

// ---- k2(b) -------------------------------------------------------------------
__global__ void __launch_bounds__(256, 2) k2_scores()
{
    __shared__ __align__(16) float Asr[KT][ASTR], Asi[KT][ASTR];
    __shared__ __align__(16) float Bsr[KT][NT], Bsi[KT][NT];
    int h = blockIdx.z;
    int i0 = blockIdx.y*MT, j0 = blockIdx.x*NT;
    int tid = threadIdx.x, tx = tid & 15, ty = tid >> 4;
    const float* E1r = g_Er + (size_t)KH*Dd*Nn;
    const float* E1i = g_Ei + (size_t)KH*Dd*Nn;
    const float* E0r = g_Er;
    const float* E0i = g_Ei;
    u64 crp[4][4] = {}, cip[4][4] = {};
    for (int l0 = 0; l0 < KH*QDq; l0 += KT) {
        #pragma unroll
        for (int it = 0; it < 2; it++) {
            int g = tid + it*256, lk = g >> 5, ic = (g & 31)*4;
            int l = l0 + lk, kq = l >> 6, q = l & 63;
            size_t ro = (size_t)(kq*Dd + h*QDq + q)*Nn;
            *(float4*)&Asr[lk][ic] = *(const float4*)&E1r[ro + i0 + ic];
            *(float4*)&Asi[lk][ic] = *(const float4*)&E1i[ro + i0 + ic];
        }
        {
            int kk = tid >> 4, nc = (tid & 15)*4;
            int l = l0 + kk, kq = l >> 6, q = l & 63;
            size_t ro = (size_t)(kq*Dd + h*QDq + q)*Nn;
            *(float4*)&Bsr[kk][nc] = *(const float4*)&E0r[ro + j0 + nc];
            float4 c4 = *(const float4*)&E0i[ro + j0 + nc];
            *(float4*)&Bsi[kk][nc] = make_float4(-c4.x,-c4.y,-c4.z,-c4.w);
        }
        __syncthreads();
        #pragma unroll
        for (int kk = 0; kk < KT; kk++) {
            F4U ar0, ar1, ai0, ai1;
            ar0.f = *(const float4*)&Asr[kk][ty*8];
            ar1.f = *(const float4*)&Asr[kk][ty*8+4];
            ai0.f = *(const float4*)&Asi[kk][ty*8];
            ai1.f = *(const float4*)&Asi[kk][ty*8+4];
            u64 apr[4] = {ar0.u[0], ar0.u[1], ar1.u[0], ar1.u[1]};
            u64 api[4] = {ai0.u[0], ai0.u[1], ai1.u[0], ai1.u[1]};
            float4 brv = *(const float4*)&Bsr[kk][tx*4];
            float4 biv = *(const float4*)&Bsi[kk][tx*4];
            float brs[4] = {brv.x,brv.y,brv.z,brv.w};
            float bis[4] = {biv.x,biv.y,biv.z,biv.w};
            #pragma unroll
            for (int j = 0; j < 4; j++) {
                u64 bpr, bpi, bpn;
                PK2(bpr, brs[j]); PK2(bpi, bis[j]);
                float nb = -bis[j]; PK2(bpn, nb);
                #pragma unroll
                for (int mi = 0; mi < 4; mi++) {
                    FMA2(crp[mi][j], apr[mi], bpr);
                    FMA2(crp[mi][j], api[mi], bpn);
                    FMA2(cip[mi][j], apr[mi], bpi);
                    FMA2(cip[mi][j], api[mi], bpr);
                }
            }
        }
        __syncthreads();
    }
    #pragma unroll
    for (int j = 0; j < 4; j++) {
        int jj = j0 + tx*4 + j;
        float s, c;
        sincosf(-THETAF * (float)jj, &s, &c);
        float wr = c, wi = s, curr = 1.f, curi = 0.f;
        #pragma unroll
        for (int kq = 0; kq < KH; kq++) {
            u64 cp, sp, sn;
            PK2(cp, curr); PK2(sp, curi);
            float ns = -curi; PK2(sn, ns);
            #pragma unroll
            for (int mi = 0; mi < 4; mi++) {
                int i = i0 + ty*8 + mi*2;
                int off = (kq*NHh + h)*Nn + i;
                u64 ppr = *(const u64*)&g_Pr[off];
                u64 ppi = *(const u64*)&g_Pi[off];
                FMA2(crp[mi][j], ppr, cp);
                FMA2(crp[mi][j], ppi, sn);
                FMA2(cip[mi][j], ppr, sp);
                FMA2(cip[mi][j], ppi, cp);
            }
            float nr = curr*wr - curi*wi;
            curi = curr*wi + curi*wr;
            curr = nr;
        }
    }
    float* So = g_S + (size_t)h*Nn*Nn;
    #pragma unroll
    for (int r = 0; r < 8; r++) {
        int i = i0 + ty*8 + r, mi = r >> 1, hi = r & 1;
        float sv[4];
        #pragma unroll
        for (int j = 0; j < 4; j++) {
            float2 c2r = unp2(crp[mi][j]), c2i = unp2(cip[mi][j]);
            float cr = hi ? c2r.y : c2r.x, ci = hi ? c2i.y : c2i.x;
            sv[j] = sqrtf(cr*cr + ci*ci) * 0.125f;
        }
        *(float4*)&So[(size_t)i*Nn + j0 + tx*4] = make_float4(sv[0],sv[1],sv[2],sv[3]);
    }
}

// ---- k3(b) -------------------------------------------------------------------
__global__ void k3_softmax()
{
    __shared__ __align__(16) float red[8][33];
    int h = blockIdx.y;
    int tx = threadIdx.x, ty = threadIdx.y;
    int j = blockIdx.x*32 + tx;
    size_t base = (size_t)h*Nn*Nn;
    float mx = -1e30f;
    for (int i = ty; i < Nn; i += 8)
        mx = fmaxf(mx, g_S[base + (size_t)i*Nn + j]);
    red[ty][tx] = mx;
    __syncthreads();
    if (ty == 0) {
        float m = red[0][tx];
        #pragma unroll
        for (int r = 1; r < 8; r++) m = fmaxf(m, red[r][tx]);
        red[0][tx] = m;
    }
    __syncthreads();
    mx = red[0][tx];
    __syncthreads();
    float sum = 0.f;
    for (int i = ty; i < Nn; i += 8) {
        size_t o = base + (size_t)i*Nn + j;
        float e = expf(g_S[o] - mx);
        g_S[o] = e;
        sum += e;
    }
    red[ty][tx] = sum;
    __syncthreads();
    if (ty == 0) {
        float s = red[0][tx];
        #pragma unroll
        for (int r = 1; r < 8; r++) s += red[r][tx];
        red[0][tx] = s;
    }
    __syncthreads();
    float inv = 1.0f / red[0][tx];
    for (int i = ty; i < Nn; i += 8)
        g_S[base + (size_t)i*Nn + j] *= inv;
}

// ---- k4(b) -------------------------------------------------------------------
__global__ void __launch_bounds__(256, 2) k4_ctx()
{
    __shared__ __align__(16) float Asr[KT][ASTR], Asi[KT][ASTR];
    __shared__ __align__(16) float Bs[KT][NT];
    int h = blockIdx.z;
    int m0 = blockIdx.y*MT, j0 = blockIdx.x*NT;
    int tid = threadIdx.x, tx = tid & 15, ty = tid >> 4;
    const float* Vr = g_Er + (size_t)(2*KH)*Dd*Nn;
    const float* Vi = g_Ei + (size_t)(2*KH)*Dd*Nn;
    const float* S  = g_S + (size_t)h*Nn*Nn;
    u64 crp[4][4] = {}, cip[4][4] = {};
    for (int c0 = 0; c0 < Nn; c0 += KT) {
        #pragma unroll
        for (int it = 0; it < 2; it++) {
            int g = tid + it*256, m = g >> 2, kc = (g & 3)*4;
            int l = m0 + m, kq = l >> 6, q = l & 63;
            size_t ro = (size_t)(kq*Dd + h*QDq + q)*Nn;
            float4 a4 = *(const float4*)&Vr[ro + c0 + kc];
            Asr[kc+0][m]=a4.x; Asr[kc+1][m]=a4.y; Asr[kc+2][m]=a4.z; Asr[kc+3][m]=a4.w;
            float4 b4 = *(const float4*)&Vi[ro + c0 + kc];
            Asi[kc+0][m]=b4.x; Asi[kc+1][m]=b4.y; Asi[kc+2][m]=b4.z; Asi[kc+3][m]=b4.w;
        }
        {
            int kk = tid >> 4, nc = (tid & 15)*4;
            *(float4*)&Bs[kk][nc] = *(const float4*)&S[(size_t)(c0+kk)*Nn + j0 + nc];
        }
        __syncthreads();
        #pragma unroll
        for (int kk = 0; kk < KT; kk++) {
            F4U ar0, ar1, ai0, ai1;
            ar0.f = *(const float4*)&Asr[kk][ty*8];
            ar1.f = *(const float4*)&Asr[kk][ty*8+4];
            ai0.f = *(const float4*)&Asi[kk][ty*8];
            ai1.f = *(const float4*)&Asi[kk][ty*8+4];
            u64 apr[4] = {ar0.u[0], ar0.u[1], ar1.u[0], ar1.u[1]};
            u64 api[4] = {ai0.u[0], ai0.u[1], ai1.u[0], ai1.u[1]};
            float4 bv = *(const float4*)&Bs[kk][tx*4];
            float bs[4] = {bv.x,bv.y,bv.z,bv.w};
            #pragma unroll
            for (int j = 0; j < 4; j++) {
                u64 bp; PK2(bp, bs[j]);
                #pragma unroll
                for (int mi = 0; mi < 4; mi++) {
                    FMA2(crp[mi][j], apr[mi], bp);
                    FMA2(cip[mi][j], api[mi], bp);
                }
            }
        }
        __syncthreads();
    }
    #pragma unroll
    for (int r = 0; r < 8; r++) {
        int l = m0 + ty*8 + r, mi = r >> 1, hi = r & 1;
        int kq = l >> 6, q = l & 63;
        size_t ro = (size_t)(kq*Cd + h*QDq + q)*Nn;
        float vr[4], vi[4];
        #pragma unroll
        for (int j = 0; j < 4; j++) {
            float2 c2r = unp2(crp[mi][j]), c2i = unp2(cip[mi][j]);
            vr[j] = hi ? c2r.y : c2r.x;
            vi[j] = hi ? c2i.y : c2i.x;
        }
        *(float4*)&g_ctxr[ro + j0 + tx*4] = make_float4(vr[0],vr[1],vr[2],vr[3]);
        *(float4*)&g_ctxi[ro + j0 + tx*4] = make_float4(vi[0],vi[1],vi[2],vi[3]);
    }
}

// ---- k5(b) -------------------------------------------------------------------
__global__ void __launch_bounds__(256, 2)
k5_out(const float* __restrict__ outr, const float* __restrict__ outi,
       float* __restrict__ res, int n_res, int b)
{
    __shared__ __align__(16) float Asr[KT][ASTR], Asi[KT][ASTR];
    __shared__ __align__(16) float Bsr[KT][NT], Bsi[KT][NT];
    int k = blockIdx.z;
    const float* Ar = outr + (size_t)k*Dd*Cd;
    const float* Ai = outi + (size_t)k*Dd*Cd;
    const float* Br = g_ctxr + (size_t)k*Cd*Nn;
    const float* Bi = g_ctxi + (size_t)k*Cd*Nn;
    int m0 = blockIdx.y*MT, n0 = blockIdx.x*NT;
    int tid = threadIdx.x, tx = tid & 15, ty = tid >> 4;
    u64 crp[4][4] = {};
    for (int c0 = 0; c0 < Cd; c0 += KT) {
        #pragma unroll
        for (int it = 0; it < 2; it++) {
            int g = tid + it*256, m = g >> 2, kc = (g & 3)*4;
            float4 a4 = *(const float4*)&Ar[(size_t)(m0+m)*Cd + c0 + kc];
            Asr[kc+0][m]=a4.x; Asr[kc+1][m]=a4.y; Asr[kc+2][m]=a4.z; Asr[kc+3][m]=a4.w;
            float4 b4 = *(const float4*)&Ai[(size_t)(m0+m)*Cd + c0 + kc];
            Asi[kc+0][m]=b4.x; Asi[kc+1][m]=b4.y; Asi[kc+2][m]=b4.z; Asi[kc+3][m]=b4.w;
        }
        {
            int kk = tid >> 4, nc = (tid & 15)*4;
            *(float4*)&Bsr[kk][nc] = *(const float4*)&Br[(size_t)(c0+kk)*Nn + n0 + nc];
            *(float4*)&Bsi[kk][nc] = *(const float4*)&Bi[(size_t)(c0+kk)*Nn + n0 + nc];
        }
        __syncthreads();
        #pragma unroll
        for (int kk = 0; kk < KT; kk++) {
            F4U ar0, ar1, ai0, ai1;
            ar0.f = *(const float4*)&Asr[kk][ty*8];
            ar1.f = *(const float4*)&Asr[kk][ty*8+4];
            ai0.f = *(const float4*)&Asi[kk][ty*8];
            ai1.f = *(const float4*)&Asi[kk][ty*8+4];
            u64 apr[4] = {ar0.u[0], ar0.u[1], ar1.u[0], ar1.u[1]};
            u64 api[4] = {ai0.u[0], ai0.u[1], ai1.u[0], ai1.u[1]};
            float4 brv = *(const float4*)&Bsr[kk][tx*4];
            float4 biv = *(const float4*)&Bsi[kk][tx*4];
            float brs[4] = {brv.x,brv.y,brv.z,brv.w};
            float bis[4] = {biv.x,biv.y,biv.z,biv.w};
            #pragma unroll
            for (int j = 0; j < 4; j++) {
                u64 bpr, bpn;
                PK2(bpr, brs[j]);
                float nb = -bis[j]; PK2(bpn, nb);
                #pragma unroll
                for (int mi = 0; mi < 4; mi++) {
                    FMA2(crp[mi][j], apr[mi], bpr);
                    FMA2(crp[mi][j], api[mi], bpn);
                }
            }
        }
        __syncthreads();
    }
    int nlim = n_res < OUT_ELEMS ? n_res : OUT_ELEMS;
    #pragma unroll
    for (int r = 0; r < 8; r++) {
        int m = m0 + ty*8 + r, mi = r >> 1, hi = r & 1;
        size_t rowo = ((size_t)(b*KH + k)*Dd + m)*Nn;
        float v[4];
        #pragma unroll
        for (int j = 0; j < 4; j++) {
            float2 c2 = unp2(crp[mi][j]);
            v[j] = hi ? c2.y : c2.x;
        }
        size_t o = rowo + n0 + tx*4;
        if (o + 4 <= (size_t)nlim) {
            *(float4*)&res[o] = make_float4(v[0],v[1],v[2],v[3]);
        } else {
            #pragma unroll
            for (int j = 0; j < 4; j++)
                if (o + j < (size_t)nlim) res[o + j] = v[j];
        }
    }
}

// ---------------- launch -----------------------------------------------------
static int classify_sz(int sz, int* elems) {
    switch (sz) {
        case 8388608:  *elems = sz;   return 0;
        case 33554432: *elems = sz/4; return 0;
        case 3145728:  *elems = sz;   return 1;
        case 12582912: *elems = sz/4; return 1;
        case 2048:     *elems = sz;   return 2;
        case 8192:     *elems = sz/4; return 2;
        case 32:       *elems = sz;   return 3;
        case 128:      *elems = sz/4; return 3;
        case 1048576:  *elems = sz;   return 4;
        case 4194304:  *elems = sz/4; return 4;
        default: *elems = 0; return -1;
    }
}

extern "C" void kernel_launch(void* const* d_in, const int* in_sizes, int n_in,
                              void* d_out, int out_size)
{
    const float* pairs[5][2] = {};
    int psz[5][2] = {};
    int cnt[5] = {};
    bool ok = (n_in == 10) && d_out;
    if (ok) for (int i = 0; i < n_in; i++) if (!d_in[i]) ok = false;

    if (ok) {
        for (int i = 0; i < n_in; i++) {
            int el; int c = classify_sz(in_sizes[i], &el);
            if (c < 0 || cnt[c] >= 2) { ok = false; break; }
            pairs[c][cnt[c]] = (const float*)d_in[i];
            psz[c][cnt[c]] = el;
            cnt[c]++;
        }
        if (ok) for (int c = 0; c < 5; c++) if (cnt[c] != 2) ok = false;
    }

    const float *xr, *xi, *embr, *embi, *encr, *enci, *softr, *softi, *outr, *outi;
    int nencr, nenci, nsoftr, nsofti;
    if (ok) {
        int el0; int c0 = classify_sz(in_sizes[0], &el0);
        int ri = (c0 == 1) ? 1 : 0;
        int im = 1 - ri;
        xr    = pairs[0][ri]; xi    = pairs[0][im];
        embr  = pairs[1][ri]; embi  = pairs[1][im];
        encr  = pairs[2][ri]; nencr  = psz[2][ri]; enci  = pairs[2][im]; nenci  = psz[2][im];
        softr = pairs[3][ri]; nsoftr = psz[3][ri]; softi = pairs[3][im]; nsofti = psz[3][im];
        outr  = pairs[4][ri]; outi  = pairs[4][im];
    } else if (n_in >= 10 && d_out) {
        xr    = (const float*)d_in[0]; xi    = (const float*)d_in[1];
        embr  = (const float*)d_in[2]; embi  = (const float*)d_in[3];
        encr  = (const float*)d_in[4]; nencr  = in_sizes[4];
        enci  = (const float*)d_in[5]; nenci  = in_sizes[5];
        softr = (const float*)d_in[6]; nsoftr = in_sizes[6];
        softi = (const float*)d_in[7]; nsofti = in_sizes[7];
        outr  = (const float*)d_in[8]; outi  = (const float*)d_in[9];
    } else {
        return;
    }

    cudaFuncSetAttribute(k1_mma, cudaFuncAttributeMaxDynamicSharedMemorySize, K1_SMEM);

    for (int b = 0; b < Bn; b++) {
        k1_mma<<<dim3(Nn/128, Dd/128, 3*KH), 512, K1_SMEM>>>(embr, embi, xr, xi,
                                                             softr, softi, b);
        kP_pos<<<dim3(Nn/256, KH*NHh), 256>>>(encr, enci, softr, softi,
                                              nencr, nenci, nsoftr, nsofti);
        k2_scores<<<dim3(Nn/NT, Nn/MT, NHh), 256>>>();
        k3_softmax<<<dim3(Nn/32, NHh), dim3(32, 8)>>>();
        k4_ctx<<<dim3(Nn/NT, (KH*QDq)/MT, NHh), 256>>>();
        k5_out<<<dim3(Nn/NT, Dd/MT, KH), 256>>>(outr, outi, (float*)d_out, out_size, b);
    }
}

// round 12
// speedup vs baseline: 1.4621x; 1.2772x over previous
#include <cuda_runtime.h>
#include <cuda_bf16.h>
#include <math.h>

#define Bn 4
#define KH 4
#define Cd 512
#define Dd 512
#define Nn 1024
#define NHh 8
#define QDq 64
#define THETAF (6.2831853071795865f / 1024.0f)
#define OUT_ELEMS 8388608

#define MT 128
#define NT 64
#define KT 16
#define ASTR 132

// ---------------- scratch (all batches; ~395 MB) -----------------------------
__device__ float g_Er[(size_t)Bn*3*KH*Dd*Nn];
__device__ float g_Ei[(size_t)Bn*3*KH*Dd*Nn];
__device__ float g_S [(size_t)Bn*NHh*Nn*Nn];
__device__ float g_Pr[Bn*KH*NHh*Nn];
__device__ float g_Pi[Bn*KH*NHh*Nn];
__device__ float g_ctxr[(size_t)Bn*KH*Cd*Nn];
__device__ float g_ctxi[(size_t)Bn*KH*Cd*Nn];

typedef unsigned long long u64;
typedef unsigned int u32;
union F4U { float4 f; u64 u[2]; };

#define PK2(d, x) asm("mov.b64 %0, {%1, %1};" : "=l"(d) : "f"(x))
#define FMA2(d, a, b) asm("fma.rn.f32x2 %0, %1, %2, %0;" : "+l"(d) : "l"(a), "l"(b))

static __device__ __forceinline__ float2 unp2(u64 v) {
    float2 r; asm("mov.b64 {%0, %1}, %2;" : "=f"(r.x), "=f"(r.y) : "l"(v)); return r;
}
static __device__ __forceinline__ float ldin(const float* p, int off, int n) {
    return (off >= 0 && off < n) ? p[off] : 0.0f;
}
static __device__ __forceinline__ u32 smem_u32(const void* p) {
    u32 a; asm("{ .reg .u64 t; cvta.to.shared.u64 t, %1; cvt.u32.u64 %0, t; }"
               : "=r"(a) : "l"(p));
    return a;
}

// ---------------- mma.sync helpers (baseline PTX, sm_103-safe) --------------
#define LDSM4(r, a) asm volatile( \
    "ldmatrix.sync.aligned.m8n8.x4.shared.b16 {%0,%1,%2,%3}, [%4];" \
    : "=r"((r)[0]),"=r"((r)[1]),"=r"((r)[2]),"=r"((r)[3]) : "r"(a))
#define LDSM2T(r, a) asm volatile( \
    "ldmatrix.sync.aligned.m8n8.x2.trans.shared.b16 {%0,%1}, [%2];" \
    : "=r"((r)[0]),"=r"((r)[1]) : "r"(a))
#define MMABF(d, a, b) asm volatile( \
    "mma.sync.aligned.m16n8k16.row.col.f32.bf16.bf16.f32 " \
    "{%0,%1,%2,%3},{%4,%5,%6,%7},{%8,%9},{%0,%1,%2,%3};" \
    : "+f"((d)[0]),"+f"((d)[1]),"+f"((d)[2]),"+f"((d)[3]) \
    : "r"((a)[0]),"r"((a)[1]),"r"((a)[2]),"r"((a)[3]),"r"((b)[0]),"r"((b)[1]))

static __device__ __forceinline__ unsigned short bfh(float v) {
    __nv_bfloat16 h = __float2bfloat16(v);
    return *(unsigned short*)&h;
}
static __device__ __forceinline__ float bf2f(unsigned short s) {
    __nv_bfloat16 h = *(__nv_bfloat16*)&s;
    return __bfloat162float(h);
}
static __device__ __forceinline__ void split2(float v, unsigned short* o) {
    unsigned short h = bfh(v);
    o[0] = h; o[1] = bfh(v - bf2f(h));
}

#define APL 10240          // A plane: 128 rows * 80 B
#define BPL 8704           // B plane: 32 rows * 272 B
#define K4_SMEM (4*APL + 2*BPL)   // 58368
#define K5_SMEM (4*APL + 4*BPL)   // 75776

// ---- k1 (FFMA2, all b): E[b,e,k,d,n] = sum_c emb[e,k,d,c]*x[b,k,c,n] -------
__global__ void __launch_bounds__(256, 2)
k1_embed(const float* __restrict__ embr, const float* __restrict__ embi,
         const float* __restrict__ xr,   const float* __restrict__ xi,
         const float* __restrict__ softr,const float* __restrict__ softi)
{
    __shared__ __align__(16) float Asr[KT][ASTR], Asi[KT][ASTR];
    __shared__ __align__(16) float Bsr[KT][NT], Bsi[KT][NT];
    int z = blockIdx.z;
    int b = z / 12, r12 = z % 12, e = r12 / KH, k = r12 % KH;
    const float* Ar = embr + (size_t)(e*KH + k)*Dd*Cd;
    const float* Ai = embi + (size_t)(e*KH + k)*Dd*Cd;
    const float* Br = xr + (size_t)(b*KH + k)*Cd*Nn;
    const float* Bi = xi + (size_t)(b*KH + k)*Cd*Nn;
    int m0 = blockIdx.y*MT, n0 = blockIdx.x*NT;
    int tid = threadIdx.x, tx = tid & 15, ty = tid >> 4;
    u64 crp[4][4] = {}, cip[4][4] = {};
    for (int c0 = 0; c0 < Cd; c0 += KT) {
        #pragma unroll
        for (int it = 0; it < 2; it++) {
            int g = tid + it*256, m = g >> 2, kc = (g & 3)*4;
            float4 a4 = *(const float4*)&Ar[(size_t)(m0+m)*Cd + c0 + kc];
            Asr[kc+0][m]=a4.x; Asr[kc+1][m]=a4.y; Asr[kc+2][m]=a4.z; Asr[kc+3][m]=a4.w;
            float4 b4 = *(const float4*)&Ai[(size_t)(m0+m)*Cd + c0 + kc];
            Asi[kc+0][m]=b4.x; Asi[kc+1][m]=b4.y; Asi[kc+2][m]=b4.z; Asi[kc+3][m]=b4.w;
        }
        {
            int kk = tid >> 4, nc = (tid & 15)*4;
            *(float4*)&Bsr[kk][nc] = *(const float4*)&Br[(size_t)(c0+kk)*Nn + n0 + nc];
            *(float4*)&Bsi[kk][nc] = *(const float4*)&Bi[(size_t)(c0+kk)*Nn + n0 + nc];
        }
        __syncthreads();
        #pragma unroll
        for (int kk = 0; kk < KT; kk++) {
            F4U ar0, ar1, ai0, ai1;
            ar0.f = *(const float4*)&Asr[kk][ty*8];
            ar1.f = *(const float4*)&Asr[kk][ty*8+4];
            ai0.f = *(const float4*)&Asi[kk][ty*8];
            ai1.f = *(const float4*)&Asi[kk][ty*8+4];
            u64 apr[4] = {ar0.u[0], ar0.u[1], ar1.u[0], ar1.u[1]};
            u64 api[4] = {ai0.u[0], ai0.u[1], ai1.u[0], ai1.u[1]};
            float4 brv = *(const float4*)&Bsr[kk][tx*4];
            float4 biv = *(const float4*)&Bsi[kk][tx*4];
            float brs[4] = {brv.x,brv.y,brv.z,brv.w};
            float bis[4] = {biv.x,biv.y,biv.z,biv.w};
            #pragma unroll
            for (int j = 0; j < 4; j++) {
                u64 bpr, bpi, bpn;
                PK2(bpr, brs[j]); PK2(bpi, bis[j]);
                float nb = -bis[j]; PK2(bpn, nb);
                #pragma unroll
                for (int mi = 0; mi < 4; mi++) {
                    FMA2(crp[mi][j], apr[mi], bpr);
                    FMA2(crp[mi][j], api[mi], bpn);
                    FMA2(cip[mi][j], apr[mi], bpi);
                    FMA2(cip[mi][j], api[mi], bpr);
                }
            }
        }
        __syncthreads();
    }
    float* Eor = g_Er + ((size_t)(b*3 + e)*KH + k)*Dd*Nn;
    float* Eoi = g_Ei + ((size_t)(b*3 + e)*KH + k)*Dd*Nn;
    #pragma unroll
    for (int r = 0; r < 8; r++) {
        int m = m0 + ty*8 + r, mi = r >> 1, hi = r & 1;
        float sr = 1.f, si = 0.f;
        if (e == 1) { int h = m >> 6; sr = softr[k*NHh+h]; si = softi[k*NHh+h]; }
        float vr[4], vi[4];
        #pragma unroll
        for (int j = 0; j < 4; j++) {
            float2 c2r = unp2(crp[mi][j]), c2i = unp2(cip[mi][j]);
            float cr = hi ? c2r.y : c2r.x, ci = hi ? c2i.y : c2i.x;
            vr[j] = cr*sr - ci*si; vi[j] = cr*si + ci*sr;
        }
        *(float4*)&Eor[(size_t)m*Nn + n0 + tx*4] = make_float4(vr[0],vr[1],vr[2],vr[3]);
        *(float4*)&Eoi[(size_t)m*Nn + n0 + tx*4] = make_float4(vi[0],vi[1],vi[2],vi[3]);
    }
}

// ---- kP (all b) --------------------------------------------------------------
__global__ void kP_pos(const float* __restrict__ encr, const float* __restrict__ enci,
                       const float* __restrict__ softr,const float* __restrict__ softi,
                       int n_encr, int n_enci, int n_softr, int n_softi)
{
    int y = blockIdx.y;
    int b = y / (KH*NHh), k = (y / NHh) % KH, h = y % NHh;
    int i = blockIdx.x*256 + threadIdx.x;
    size_t e0 = (size_t)(b*3)*KH*Dd*Nn + (size_t)(k*Dd + h*QDq)*Nn;
    const float* E0r = g_Er + e0;
    const float* E0i = g_Ei + e0;
    float accr = 0.f, acci = 0.f;
    for (int q = 0; q < QDq; q++) {
        float er = E0r[(size_t)q*Nn + i], ei = E0i[(size_t)q*Nn + i];
        float nr = ldin(encr, (k*NHh + h)*QDq + q, n_encr);
        float ni = ldin(enci, (k*NHh + h)*QDq + q, n_enci);
        accr += er*nr + ei*ni;
        acci += er*ni - ei*nr;
    }
    float sr = ldin(softr, k*NHh + h, n_softr);
    float si = ldin(softi, k*NHh + h, n_softi);
    float tr = accr*sr - acci*si, ti = accr*si + acci*sr;
    float s, c;
    sincosf(THETAF * (float)(k*i), &s, &c);
    int o = ((b*KH + k)*NHh + h)*Nn + i;
    g_Pr[o] = tr*c - ti*s;
    g_Pi[o] = tr*s + ti*c;
}

// ---- k2 (all b): S[b,h,i,j] = |GEMM + pos| / 8 -------------------------------
__global__ void __launch_bounds__(256, 2) k2_scores()
{
    __shared__ __align__(16) float Asr[KT][ASTR], Asi[KT][ASTR];
    __shared__ __align__(16) float Bsr[KT][NT], Bsi[KT][NT];
    int z = blockIdx.z;
    int b = z >> 3, h = z & 7;
    int i0 = blockIdx.y*MT, j0 = blockIdx.x*NT;
    int tid = threadIdx.x, tx = tid & 15, ty = tid >> 4;
    const float* E1r = g_Er + (size_t)(b*3 + 1)*KH*Dd*Nn;
    const float* E1i = g_Ei + (size_t)(b*3 + 1)*KH*Dd*Nn;
    const float* E0r = g_Er + (size_t)(b*3)*KH*Dd*Nn;
    const float* E0i = g_Ei + (size_t)(b*3)*KH*Dd*Nn;
    u64 crp[4][4] = {}, cip[4][4] = {};
    for (int l0 = 0; l0 < KH*QDq; l0 += KT) {
        #pragma unroll
        for (int it = 0; it < 2; it++) {
            int g = tid + it*256, lk = g >> 5, ic = (g & 31)*4;
            int l = l0 + lk, kq = l >> 6, q = l & 63;
            size_t ro = (size_t)(kq*Dd + h*QDq + q)*Nn;
            *(float4*)&Asr[lk][ic] = *(const float4*)&E1r[ro + i0 + ic];
            *(float4*)&Asi[lk][ic] = *(const float4*)&E1i[ro + i0 + ic];
        }
        {
            int kk = tid >> 4, nc = (tid & 15)*4;
            int l = l0 + kk, kq = l >> 6, q = l & 63;
            size_t ro = (size_t)(kq*Dd + h*QDq + q)*Nn;
            *(float4*)&Bsr[kk][nc] = *(const float4*)&E0r[ro + j0 + nc];
            float4 c4 = *(const float4*)&E0i[ro + j0 + nc];
            *(float4*)&Bsi[kk][nc] = make_float4(-c4.x,-c4.y,-c4.z,-c4.w);
        }
        __syncthreads();
        #pragma unroll
        for (int kk = 0; kk < KT; kk++) {
            F4U ar0, ar1, ai0, ai1;
            ar0.f = *(const float4*)&Asr[kk][ty*8];
            ar1.f = *(const float4*)&Asr[kk][ty*8+4];
            ai0.f = *(const float4*)&Asi[kk][ty*8];
            ai1.f = *(const float4*)&Asi[kk][ty*8+4];
            u64 apr[4] = {ar0.u[0], ar0.u[1], ar1.u[0], ar1.u[1]};
            u64 api[4] = {ai0.u[0], ai0.u[1], ai1.u[0], ai1.u[1]};
            float4 brv = *(const float4*)&Bsr[kk][tx*4];
            float4 biv = *(const float4*)&Bsi[kk][tx*4];
            float brs[4] = {brv.x,brv.y,brv.z,brv.w};
            float bis[4] = {biv.x,biv.y,biv.z,biv.w};
            #pragma unroll
            for (int j = 0; j < 4; j++) {
                u64 bpr, bpi, bpn;
                PK2(bpr, brs[j]); PK2(bpi, bis[j]);
                float nb = -bis[j]; PK2(bpn, nb);
                #pragma unroll
                for (int mi = 0; mi < 4; mi++) {
                    FMA2(crp[mi][j], apr[mi], bpr);
                    FMA2(crp[mi][j], api[mi], bpn);
                    FMA2(cip[mi][j], apr[mi], bpi);
                    FMA2(cip[mi][j], api[mi], bpr);
                }
            }
        }
        __syncthreads();
    }
    #pragma unroll
    for (int j = 0; j < 4; j++) {
        int jj = j0 + tx*4 + j;
        float s, c;
        sincosf(-THETAF * (float)jj, &s, &c);
        float wr = c, wi = s, curr = 1.f, curi = 0.f;
        #pragma unroll
        for (int kq = 0; kq < KH; kq++) {
            u64 cp, sp, sn;
            PK2(cp, curr); PK2(sp, curi);
            float ns = -curi; PK2(sn, ns);
            #pragma unroll
            for (int mi = 0; mi < 4; mi++) {
                int i = i0 + ty*8 + mi*2;
                int off = ((b*KH + kq)*NHh + h)*Nn + i;
                u64 ppr = *(const u64*)&g_Pr[off];
                u64 ppi = *(const u64*)&g_Pi[off];
                FMA2(crp[mi][j], ppr, cp);
                FMA2(crp[mi][j], ppi, sn);
                FMA2(cip[mi][j], ppr, sp);
                FMA2(cip[mi][j], ppi, cp);
            }
            float nr = curr*wr - curi*wi;
            curi = curr*wi + curi*wr;
            curr = nr;
        }
    }
    float* So = g_S + (size_t)(b*NHh + h)*Nn*Nn;
    #pragma unroll
    for (int r = 0; r < 8; r++) {
        int i = i0 + ty*8 + r, mi = r >> 1, hi = r & 1;
        float sv[4];
        #pragma unroll
        for (int j = 0; j < 4; j++) {
            float2 c2r = unp2(crp[mi][j]), c2i = unp2(cip[mi][j]);
            float cr = hi ? c2r.y : c2r.x, ci = hi ? c2i.y : c2i.x;
            sv[j] = sqrtf(cr*cr + ci*ci) * 0.125f;
        }
        *(float4*)&So[(size_t)i*Nn + j0 + tx*4] = make_float4(sv[0],sv[1],sv[2],sv[3]);
    }
}

// ---- k3 (all b): softmax over i, per (b,h,j) ---------------------------------
__global__ void k3_softmax()
{
    __shared__ __align__(16) float red[8][33];
    int y = blockIdx.y;
    int b = y >> 3, h = y & 7;
    int tx = threadIdx.x, ty = threadIdx.y;
    int j = blockIdx.x*32 + tx;
    size_t base = (size_t)(b*NHh + h)*Nn*Nn;
    float mx = -1e30f;
    for (int i = ty; i < Nn; i += 8)
        mx = fmaxf(mx, g_S[base + (size_t)i*Nn + j]);
    red[ty][tx] = mx;
    __syncthreads();
    if (ty == 0) {
        float m = red[0][tx];
        #pragma unroll
        for (int r = 1; r < 8; r++) m = fmaxf(m, red[r][tx]);
        red[0][tx] = m;
    }
    __syncthreads();
    mx = red[0][tx];
    __syncthreads();
    float sum = 0.f;
    for (int i = ty; i < Nn; i += 8) {
        size_t o = base + (size_t)i*Nn + j;
        float e = expf(g_S[o] - mx);
        g_S[o] = e;
        sum += e;
    }
    red[ty][tx] = sum;
    __syncthreads();
    if (ty == 0) {
        float s = red[0][tx];
        #pragma unroll
        for (int r = 1; r < 8; r++) s += red[r][tx];
        red[0][tx] = s;
    }
    __syncthreads();
    float inv = 1.0f / red[0][tx];
    for (int i = ty; i < Nn; i += 8)
        g_S[base + (size_t)i*Nn + j] *= inv;
}

// ---- k4 (mma 2-split): ctx[b,k,h,q,j] = sum_i V[b,k,h,q,i]*S[b,h,i,j] ------
__global__ void __launch_bounds__(512, 1) k4_mma()
{
    extern __shared__ char sm[];
    u32 smA = smem_u32(sm);
    u32 smB = smA + 4*APL;
    int tid = threadIdx.x, wid = tid >> 5, lane = tid & 31;
    int wm = wid >> 2, wn = wid & 3;
    int z = blockIdx.z, b = z >> 3, h = z & 7;
    int m0 = blockIdx.y*128, j0 = blockIdx.x*128;
    const float* Vr = g_Er + (size_t)(b*3 + 2)*KH*Dd*Nn;
    const float* Vi = g_Ei + (size_t)(b*3 + 2)*KH*Dd*Nn;
    const float* S  = g_S + (size_t)(b*NHh + h)*Nn*Nn;
    const int PA2[3] = {0, 0, 1};
    const int PB2[3] = {0, 1, 0};
    float dr[2][4][4] = {}, di[2][4][4] = {};
    u32 aRowOff = (u32)((wm*32 + (lane & 15))*80 + (lane >> 4)*16);
    u32 bColOff = (u32)(wn*64);

    for (int c0 = 0; c0 < Nn; c0 += 32) {
        #pragma unroll
        for (int it = 0; it < 2; it++) {
            int t = tid + it*512;
            int m = t >> 3, c4 = (t & 7)*4;
            int l = m0 + m, kq = l >> 6, q = l & 63;
            size_t ro = (size_t)(kq*Dd + h*QDq + q)*Nn;
            float4 vr = *(const float4*)&Vr[ro + c0 + c4];
            float4 vi = *(const float4*)&Vi[ro + c0 + c4];
            unsigned short hh[4], ll[4], s2[2];
            u32 wo = (u32)(m*80 + c4*2);
            float rs[4] = {vr.x, vr.y, vr.z, vr.w};
            #pragma unroll
            for (int j = 0; j < 4; j++) { split2(rs[j], s2); hh[j]=s2[0]; ll[j]=s2[1]; }
            *(u64*)(sm + 0*APL + wo) = (u64)hh[0] | ((u64)hh[1]<<16) | ((u64)hh[2]<<32) | ((u64)hh[3]<<48);
            *(u64*)(sm + 1*APL + wo) = (u64)ll[0] | ((u64)ll[1]<<16) | ((u64)ll[2]<<32) | ((u64)ll[3]<<48);
            float is[4] = {vi.x, vi.y, vi.z, vi.w};
            #pragma unroll
            for (int j = 0; j < 4; j++) { split2(is[j], s2); hh[j]=s2[0]; ll[j]=s2[1]; }
            *(u64*)(sm + 2*APL + wo) = (u64)hh[0] | ((u64)hh[1]<<16) | ((u64)hh[2]<<32) | ((u64)hh[3]<<48);
            *(u64*)(sm + 3*APL + wo) = (u64)ll[0] | ((u64)ll[1]<<16) | ((u64)ll[2]<<32) | ((u64)ll[3]<<48);
        }
        #pragma unroll
        for (int it = 0; it < 2; it++) {
            int t = tid + it*512;
            int c = t >> 5, n4 = (t & 31)*4;
            float4 sv = *(const float4*)&S[(size_t)(c0 + c)*Nn + j0 + n4];
            unsigned short hh[4], ll[4], s2[2];
            u32 wo = (u32)(c*272 + n4*2);
            float ss[4] = {sv.x, sv.y, sv.z, sv.w};
            #pragma unroll
            for (int j = 0; j < 4; j++) { split2(ss[j], s2); hh[j]=s2[0]; ll[j]=s2[1]; }
            char* bb = sm + 4*APL;
            *(u64*)(bb + 0*BPL + wo) = (u64)hh[0] | ((u64)hh[1]<<16) | ((u64)hh[2]<<32) | ((u64)hh[3]<<48);
            *(u64*)(bb + 1*BPL + wo) = (u64)ll[0] | ((u64)ll[1]<<16) | ((u64)ll[2]<<32) | ((u64)ll[3]<<48);
        }
        __syncthreads();
        #pragma unroll
        for (int ks = 0; ks < 2; ks++) {
            #pragma unroll
            for (int s = 0; s < 3; s++) {
                u32 ar0[4], ar1[4], ai0[4], ai1[4];
                u32 abase = smA + aRowOff + (u32)(ks*32);
                LDSM4(ar0, abase + PA2[s]*APL);
                LDSM4(ar1, abase + PA2[s]*APL + 16*80);
                LDSM4(ai0, abase + (2+PA2[s])*APL);
                LDSM4(ai1, abase + (2+PA2[s])*APL + 16*80);
                u32 bbase = smB + (u32)((ks*16 + (lane & 15))*272) + bColOff;
                #pragma unroll
                for (int nt = 0; nt < 4; nt++) {
                    u32 bb[2];
                    LDSM2T(bb, bbase + (u32)(nt*16) + PB2[s]*BPL);
                    MMABF(dr[0][nt], ar0, bb); MMABF(di[0][nt], ai0, bb);
                    MMABF(dr[1][nt], ar1, bb); MMABF(di[1][nt], ai1, bb);
                }
            }
        }
        __syncthreads();
    }
    size_t cb = (size_t)b*KH*Cd*Nn;
    #pragma unroll
    for (int mt = 0; mt < 2; mt++) {
        #pragma unroll
        for (int ch = 0; ch < 2; ch++) {
            int l = m0 + wm*32 + mt*16 + (lane >> 2) + ch*8;
            int kq = l >> 6, q = l & 63;
            size_t ro = cb + (size_t)(kq*Cd + h*QDq + q)*Nn;
            #pragma unroll
            for (int nt = 0; nt < 4; nt++) {
                int j = j0 + wn*32 + nt*8 + (lane & 3)*2;
                *(float2*)&g_ctxr[ro + j] = make_float2(dr[mt][nt][ch*2], dr[mt][nt][ch*2+1]);
                *(float2*)&g_ctxi[ro + j] = make_float2(di[mt][nt][ch*2], di[mt][nt][ch*2+1]);
            }
        }
    }
}

// ---- k5 (mma 2-split, real-only): res = Re(out[k] @ ctx[b,k]) ---------------
__global__ void __launch_bounds__(512, 1)
k5_mma(const float* __restrict__ outr, const float* __restrict__ outi,
       float* __restrict__ res, int n_res)
{
    extern __shared__ char sm[];
    u32 smA = smem_u32(sm);
    u32 smB = smA + 4*APL;
    int tid = threadIdx.x, wid = tid >> 5, lane = tid & 31;
    int wm = wid >> 2, wn = wid & 3;
    int z = blockIdx.z, b = z >> 2, k = z & 3;
    int m0 = blockIdx.y*128, j0 = blockIdx.x*128;
    const float* Ar = outr + (size_t)k*Dd*Cd;
    const float* Ai = outi + (size_t)k*Dd*Cd;
    const float* Br = g_ctxr + ((size_t)b*KH + k)*Cd*Nn;
    const float* Bi = g_ctxi + ((size_t)b*KH + k)*Cd*Nn;
    const int PA2[3] = {0, 0, 1};
    const int PB2[3] = {0, 1, 0};
    float dr[2][4][4] = {};
    u32 aRowOff = (u32)((wm*32 + (lane & 15))*80 + (lane >> 4)*16);
    u32 bColOff = (u32)(wn*64);

    for (int c0 = 0; c0 < Cd; c0 += 32) {
        #pragma unroll
        for (int it = 0; it < 2; it++) {
            int t = tid + it*512;
            int m = t >> 3, c4 = (t & 7)*4;
            float4 vr = *(const float4*)&Ar[(size_t)(m0+m)*Cd + c0 + c4];
            float4 vi = *(const float4*)&Ai[(size_t)(m0+m)*Cd + c0 + c4];
            unsigned short hh[4], ll[4], s2[2];
            u32 wo = (u32)(m*80 + c4*2);
            float rs[4] = {vr.x, vr.y, vr.z, vr.w};
            #pragma unroll
            for (int j = 0; j < 4; j++) { split2(rs[j], s2); hh[j]=s2[0]; ll[j]=s2[1]; }
            *(u64*)(sm + 0*APL + wo) = (u64)hh[0] | ((u64)hh[1]<<16) | ((u64)hh[2]<<32) | ((u64)hh[3]<<48);
            *(u64*)(sm + 1*APL + wo) = (u64)ll[0] | ((u64)ll[1]<<16) | ((u64)ll[2]<<32) | ((u64)ll[3]<<48);
            float is[4] = {-vi.x, -vi.y, -vi.z, -vi.w};   // negated imag
            #pragma unroll
            for (int j = 0; j < 4; j++) { split2(is[j], s2); hh[j]=s2[0]; ll[j]=s2[1]; }
            *(u64*)(sm + 2*APL + wo) = (u64)hh[0] | ((u64)hh[1]<<16) | ((u64)hh[2]<<32) | ((u64)hh[3]<<48);
            *(u64*)(sm + 3*APL + wo) = (u64)ll[0] | ((u64)ll[1]<<16) | ((u64)ll[2]<<32) | ((u64)ll[3]<<48);
        }
        #pragma unroll
        for (int it = 0; it < 2; it++) {
            int t = tid + it*512;
            int c = t >> 5, n4 = (t & 31)*4;
            size_t go = (size_t)(c0 + c)*Nn + j0 + n4;
            float4 vr = *(const float4*)&Br[go];
            float4 vi = *(const float4*)&Bi[go];
            unsigned short hh[4], ll[4], s2[2];
            u32 wo = (u32)(c*272 + n4*2);
            char* bb = sm + 4*APL;
            float rs[4] = {vr.x, vr.y, vr.z, vr.w};
            #pragma unroll
            for (int j = 0; j < 4; j++) { split2(rs[j], s2); hh[j]=s2[0]; ll[j]=s2[1]; }
            *(u64*)(bb + 0*BPL + wo) = (u64)hh[0] | ((u64)hh[1]<<16) | ((u64)hh[2]<<32) | ((u64)hh[3]<<48);
            *(u64*)(bb + 1*BPL + wo) = (u64)ll[0] | ((u64)ll[1]<<16) | ((u64)ll[2]<<32) | ((u64)ll[3]<<48);
            float is[4] = {vi.x, vi.y, vi.z, vi.w};
            #pragma unroll
            for (int j = 0; j < 4; j++) { split2(is[j], s2); hh[j]=s2[0]; ll[j]=s2[1]; }
            *(u64*)(bb + 2*BPL + wo) = (u64)hh[0] | ((u64)hh[1]<<16) | ((u64)hh[2]<<32) | ((u64)hh[3]<<48);
            *(u64*)(bb + 3*BPL + wo) = (u64)ll[0] | ((u64)ll[1]<<16) | ((u64)ll[2]<<32) | ((u64)ll[3]<<48);
        }
        __syncthreads();
        #pragma unroll
        for (int ks = 0; ks < 2; ks++) {
            #pragma unroll
            for (int s = 0; s < 3; s++) {
                u32 ar0[4], ar1[4], an0[4], an1[4];
                u32 abase = smA + aRowOff + (u32)(ks*32);
                LDSM4(ar0, abase + PA2[s]*APL);
                LDSM4(ar1, abase + PA2[s]*APL + 16*80);
                LDSM4(an0, abase + (2+PA2[s])*APL);
                LDSM4(an1, abase + (2+PA2[s])*APL + 16*80);
                u32 bbase = smB + (u32)((ks*16 + (lane & 15))*272) + bColOff;
                #pragma unroll
                for (int nt = 0; nt < 4; nt++) {
                    u32 br[2], bi2[2];
                    u32 boff = bbase + (u32)(nt*16);
                    LDSM2T(br, boff + PB2[s]*BPL);
                    LDSM2T(bi2, boff + (2+PB2[s])*BPL);
                    MMABF(dr[0][nt], ar0, br); MMABF(dr[0][nt], an0, bi2);
                    MMABF(dr[1][nt], ar1, br); MMABF(dr[1][nt], an1, bi2);
                }
            }
        }
        __syncthreads();
    }
    int nlim = n_res < OUT_ELEMS ? n_res : OUT_ELEMS;
    #pragma unroll
    for (int mt = 0; mt < 2; mt++) {
        #pragma unroll
        for (int ch = 0; ch < 2; ch++) {
            int d = m0 + wm*32 + mt*16 + (lane >> 2) + ch*8;
            size_t row = ((size_t)(b*KH + k)*Dd + d)*Nn;
            #pragma unroll
            for (int nt = 0; nt < 4; nt++) {
                int j = j0 + wn*32 + nt*8 + (lane & 3)*2;
                size_t o = row + j;
                float v0 = dr[mt][nt][ch*2], v1 = dr[mt][nt][ch*2+1];
                if (o + 2 <= (size_t)nlim) {
                    *(float2*)&res[o] = make_float2(v0, v1);
                } else {
                    if (o < (size_t)nlim) res[o] = v0;
                    if (o + 1 < (size_t)nlim) res[o+1] = v1;
                }
            }
        }
    }
}

// ---------------- launch -----------------------------------------------------
static int classify_sz(int sz, int* elems) {
    switch (sz) {
        case 8388608:  *elems = sz;   return 0;
        case 33554432: *elems = sz/4; return 0;
        case 3145728:  *elems = sz;   return 1;
        case 12582912: *elems = sz/4; return 1;
        case 2048:     *elems = sz;   return 2;
        case 8192:     *elems = sz/4; return 2;
        case 32:       *elems = sz;   return 3;
        case 128:      *elems = sz/4; return 3;
        case 1048576:  *elems = sz;   return 4;
        case 4194304:  *elems = sz/4; return 4;
        default: *elems = 0; return -1;
    }
}

extern "C" void kernel_launch(void* const* d_in, const int* in_sizes, int n_in,
                              void* d_out, int out_size)
{
    const float* pairs[5][2] = {};
    int psz[5][2] = {};
    int cnt[5] = {};
    bool ok = (n_in == 10) && d_out;
    if (ok) for (int i = 0; i < n_in; i++) if (!d_in[i]) ok = false;

    if (ok) {
        for (int i = 0; i < n_in; i++) {
            int el; int c = classify_sz(in_sizes[i], &el);
            if (c < 0 || cnt[c] >= 2) { ok = false; break; }
            pairs[c][cnt[c]] = (const float*)d_in[i];
            psz[c][cnt[c]] = el;
            cnt[c]++;
        }
        if (ok) for (int c = 0; c < 5; c++) if (cnt[c] != 2) ok = false;
    }

    const float *xr, *xi, *embr, *embi, *encr, *enci, *softr, *softi, *outr, *outi;
    int nencr, nenci, nsoftr, nsofti;
    if (ok) {
        int el0; int c0 = classify_sz(in_sizes[0], &el0);
        int ri = (c0 == 1) ? 1 : 0;
        int im = 1 - ri;
        xr    = pairs[0][ri]; xi    = pairs[0][im];
        embr  = pairs[1][ri]; embi  = pairs[1][im];
        encr  = pairs[2][ri]; nencr  = psz[2][ri]; enci  = pairs[2][im]; nenci  = psz[2][im];
        softr = pairs[3][ri]; nsoftr = psz[3][ri]; softi = pairs[3][im]; nsofti = psz[3][im];
        outr  = pairs[4][ri]; outi  = pairs[4][im];
    } else if (n_in >= 10 && d_out) {
        xr    = (const float*)d_in[0]; xi    = (const float*)d_in[1];
        embr  = (const float*)d_in[2]; embi  = (const float*)d_in[3];
        encr  = (const float*)d_in[4]; nencr  = in_sizes[4];
        enci  = (const float*)d_in[5]; nenci  = in_sizes[5];
        softr = (const float*)d_in[6]; nsoftr = in_sizes[6];
        softi = (const float*)d_in[7]; nsofti = in_sizes[7];
        outr  = (const float*)d_in[8]; outi  = (const float*)d_in[9];
    } else {
        return;
    }

    cudaFuncSetAttribute(k4_mma, cudaFuncAttributeMaxDynamicSharedMemorySize, K4_SMEM);
    cudaFuncSetAttribute(k5_mma, cudaFuncAttributeMaxDynamicSharedMemorySize, K5_SMEM);

    k1_embed<<<dim3(Nn/NT, Dd/MT, 12*Bn), 256>>>(embr, embi, xr, xi, softr, softi);
    kP_pos<<<dim3(Nn/256, Bn*KH*NHh), 256>>>(encr, enci, softr, softi,
                                             nencr, nenci, nsoftr, nsofti);
    k2_scores<<<dim3(Nn/NT, Nn/MT, Bn*NHh), 256>>>();
    k3_softmax<<<dim3(Nn/32, Bn*NHh), dim3(32, 8)>>>();
    k4_mma<<<dim3(Nn/128, (KH*QDq)/128, Bn*NHh), 512, K4_SMEM>>>();
    k5_mma<<<dim3(Nn/128, Dd/128, Bn*KH), 512, K5_SMEM>>>(outr, outi,
                                                          (float*)d_out, out_size);
}